// round 12
// baseline (speedup 1.0000x reference)
#include <cuda_runtime.h>
#include <cuda_fp16.h>
#include <math.h>
#include <stdint.h>

// ---------------------------------------------------------------------------
// Problem constants: B=16, L=512, H=1024, G=2, NH=16, DH=64, FF=4096,
//                    DM=512, LG=256
// ---------------------------------------------------------------------------

// Scratch (device globals; allocation inside kernel_launch is forbidden)
__device__ __half g_yh   [16u*512u*1024u];   // half copy of y (GEMM A input)
__device__ __half g_wqkvT[1536u*512u];       // (N,K) transposed packed Wq|Wk|Wv
__device__ float  g_bqkv [1536u];
__device__ __half g_wmT  [1024u*1024u];      // (N,K)
__device__ __half g_w1T  [4096u*1024u];
__device__ __half g_w2T  [512u*2048u];
__device__ __half g_qkv  [16384u*1536u];     // fused QKV output (row stride 1536)
__device__ __half g_att  [16u*512u*1024u];   // attention output (GEMM A input)
__device__ float  g_mh   [16u*512u*1024u];
__device__ float  g_y1   [16u*512u*1024u];   // LN1 out fp32 (residual)
__device__ __half g_y1h  [16u*512u*1024u];   // LN1 out half (FFN1 A input)
__device__ __half g_h1   [8192u*4096u];      // FFN hidden (relu, half)
__device__ float  g_ff   [16u*512u*1024u];

// ---------------------------------------------------------------------------
// Helpers
// ---------------------------------------------------------------------------
__device__ __forceinline__ void mma_f16(float* d, const unsigned* a, const unsigned* b) {
    asm volatile(
        "mma.sync.aligned.m16n8k16.row.col.f32.f16.f16.f32 "
        "{%0,%1,%2,%3}, {%4,%5,%6,%7}, {%8,%9}, {%0,%1,%2,%3};\n"
        : "+f"(d[0]), "+f"(d[1]), "+f"(d[2]), "+f"(d[3])
        : "r"(a[0]), "r"(a[1]), "r"(a[2]), "r"(a[3]), "r"(b[0]), "r"(b[1]));
}

__device__ __forceinline__ void ldsm_x4(unsigned* r, unsigned a) {
    asm volatile("ldmatrix.sync.aligned.m8n8.x4.shared.b16 {%0,%1,%2,%3}, [%4];"
        : "=r"(r[0]), "=r"(r[1]), "=r"(r[2]), "=r"(r[3]) : "r"(a));
}
__device__ __forceinline__ void ldsm_x4_t(unsigned* r, unsigned a) {
    asm volatile("ldmatrix.sync.aligned.m8n8.x4.trans.shared.b16 {%0,%1,%2,%3}, [%4];"
        : "=r"(r[0]), "=r"(r[1]), "=r"(r[2]), "=r"(r[3]) : "r"(a));
}

__device__ __forceinline__ void cp16(unsigned dst, const void* src) {
    asm volatile("cp.async.cg.shared.global [%0], [%1], 16;\n" :: "r"(dst), "l"(src));
}
__device__ __forceinline__ void cp_commit() {
    asm volatile("cp.async.commit_group;\n" ::);
}
template<int N>
__device__ __forceinline__ void cp_wait() {
    asm volatile("cp.async.wait_group %0;\n" :: "n"(N));
}

// ---------------------------------------------------------------------------
// Fused pre-pass (unchanged from R11): all weight transposes (+half),
// y->half convert, bias pack.  Block-range dispatch.
// ---------------------------------------------------------------------------
__device__ __forceinline__ void transp_tile(const float* __restrict__ in,
                                            __half* __restrict__ out,
                                            int K, int N, int nb, int kb,
                                            float (*t)[33], int tid)
{
    int tx = tid & 31, ty = tid >> 5;
#pragma unroll
    for (int i = 0; i < 32; i += 8)
        t[ty + i][tx] = in[(size_t)(kb + ty + i) * N + nb + tx];
    __syncthreads();
#pragma unroll
    for (int i = 0; i < 32; i += 8)
        out[(size_t)(nb + ty + i) * K + kb + tx] = __float2half(t[tx][ty + i]);
}

__global__ __launch_bounds__(256)
void prep(const float* __restrict__ y, __half* __restrict__ yh,
          const float* __restrict__ Wq, const float* __restrict__ Wk,
          const float* __restrict__ Wv, __half* __restrict__ wqkvT,
          const float* __restrict__ Wm, __half* __restrict__ wmT,
          const float* __restrict__ W1, __half* __restrict__ w1T,
          const float* __restrict__ W2, __half* __restrict__ w2T,
          const float* __restrict__ bq, const float* __restrict__ bk,
          const float* __restrict__ bv, float* __restrict__ bqkv)
{
    __shared__ float t[32][33];
    const int bid = blockIdx.x;
    const int tid = threadIdx.x;

    if (bid < 768) {
        int nbt = bid % 48, kbt = bid / 48;
        int nb = nbt << 5, kb = kbt << 5;
        const float* src = (nb < 512) ? Wq : (nb < 1024) ? Wk : Wv;
        int nloc = nb & 511;
        int tx = tid & 31, ty = tid >> 5;
#pragma unroll
        for (int i = 0; i < 32; i += 8)
            t[ty + i][tx] = src[(size_t)(kb + ty + i) * 512 + nloc + tx];
        __syncthreads();
#pragma unroll
        for (int i = 0; i < 32; i += 8)
            wqkvT[(size_t)(nb + ty + i) * 512 + kb + tx] = __float2half(t[tx][ty + i]);
    } else if (bid < 1792) {
        int r = bid - 768;
        transp_tile(Wm, wmT, 1024, 1024, (r % 32) << 5, (r / 32) << 5, t, tid);
    } else if (bid < 5888) {
        int r = bid - 1792;
        transp_tile(W1, w1T, 1024, 4096, (r % 128) << 5, (r / 128) << 5, t, tid);
    } else if (bid < 6912) {
        int r = bid - 5888;
        transp_tile(W2, w2T, 2048, 512, (r % 16) << 5, (r / 16) << 5, t, tid);
    } else if (bid < 7936) {
        size_t base = (size_t)(bid - 6912) * 8192 + (tid << 2);
#pragma unroll
        for (int j = 0; j < 8; j++) {
            size_t idx = base + (size_t)j * 1024;
            float4 v = *(const float4*)&y[idx];
            __half2 h0 = __floats2half2_rn(v.x, v.y);
            __half2 h1 = __floats2half2_rn(v.z, v.w);
            *(__half2*)&yh[idx]     = h0;
            *(__half2*)&yh[idx + 2] = h1;
        }
    } else {
#pragma unroll
        for (int j = 0; j < 6; j++) {
            int i = tid + (j << 8);
            int s = i >> 9, c = i & 511;
            const float* bs = (s == 0) ? bq : (s == 1) ? bk : bv;
            bqkv[i] = bs[c];
        }
    }
}

// ---------------------------------------------------------------------------
// fp16 tensor-core GEMM (mma.sync m16n8k16, fp32 accumulate).
// Block tile 128x128, K-step 32 halves, 256 threads, 8 warps 2(M)x4(N),
// warp tile 64x32, ldmatrix.x4 fragments (pitch-40-half rows conflict-free).
// 4-stage cp.async pipeline with prefetch distance 3; next tile's copies
// issued BEFORE the MMA burst so copy overlaps compute (R11 ncu: tensor 45%,
// idle = sync/wait serialization).  80KB smem -> 2 CTAs/SM (164KB total).
// Requires M%128==0, N%128==0, K%32==0.
// ---------------------------------------------------------------------------
#define STAGES 4
#define ROW_BYTES 80                  // 40 halves/row (32 data + 8 pad)
#define A_BYTES (128 * ROW_BYTES)     // 10240
#define STAGE_BYTES (2 * A_BYTES)     // 20480
#define GEMM_SMEM_BYTES (STAGES * STAGE_BYTES)  // 81920

#define GEMM_ISSUE(s_) do {                                                   \
    int ko_ = (s_) << 5;                                                      \
    unsigned sb_ = sbase + (unsigned)(((s_) % STAGES) * STAGE_BYTES);         \
    _Pragma("unroll")                                                         \
    for (int i_ = 0; i_ < 2; i_++) cp16(sb_ + a_sm[i_], a_gm[i_] + ko_);      \
    _Pragma("unroll")                                                         \
    for (int i_ = 0; i_ < 2; i_++)                                            \
        cp16(sb_ + A_BYTES + b_sm[i_], b_gm[i_] + ko_);                       \
} while (0)

template<bool GATHER_A, bool RELU, bool OUT_HALF>
__global__ __launch_bounds__(256, 2)
void hgemm(const __half* __restrict__ A, const __half* __restrict__ BT,
           const float* __restrict__ bias, void* __restrict__ Cv,
           int M, int N, int K)
{
    extern __shared__ unsigned char dsm[];
    const unsigned sbase = (unsigned)__cvta_generic_to_shared(dsm);

    const int tid  = threadIdx.x;
    const int row0 = blockIdx.y << 7;
    const int col0 = blockIdx.x << 7;
    const int lane = tid & 31;
    const int w    = tid >> 5;
    const int wm   = w & 1;
    const int wn   = w >> 1;
    const int tig  = lane & 3;
    const int grp  = lane >> 2;

    unsigned a_sm[2], b_sm[2];
    const __half* a_gm[2];
    const __half* b_gm[2];
#pragma unroll
    for (int i = 0; i < 2; i++) {
        int ci = tid + (i << 8);
        int r  = ci >> 2;
        int kc = (ci & 3) << 3;
        a_sm[i] = (unsigned)(r * ROW_BYTES + (kc << 1));
        b_sm[i] = a_sm[i];
        int grow = row0 + r;
        if (GATHER_A) {
            int bg = grow >> 9, l = grow & 511;
            int b  = bg & 15,  g = bg >> 4;
            a_gm[i] = A + (((size_t)b * 512 + l) * 1024 + (size_t)g * 512) + kc;
        } else {
            a_gm[i] = A + (size_t)grow * (size_t)K + kc;
        }
        b_gm[i] = BT + (size_t)(col0 + r) * (size_t)K + kc;
    }

    const unsigned a_ld = (unsigned)(((wm << 6) + (lane & 15)) * ROW_BYTES
                                     + (((lane >> 4) << 3) << 1));
    const unsigned b_ld = (unsigned)((((wn << 5) + (lane & 7)) * ROW_BYTES)
                                     + ((((lane >> 3) & 3) << 3) << 1));

    float acc[4][4][4];
#pragma unroll
    for (int mi = 0; mi < 4; mi++)
#pragma unroll
        for (int ni = 0; ni < 4; ni++)
#pragma unroll
            for (int j = 0; j < 4; j++) acc[mi][ni][j] = 0.f;

    GEMM_ISSUE(0); cp_commit();
    GEMM_ISSUE(1); cp_commit();
    GEMM_ISSUE(2); cp_commit();

    const int nIter = K >> 5;
    for (int it = 0; it < nIter; ++it) {
        cp_wait<2>();
        __syncthreads();

        // overlap: issue tile it+3 BEFORE the MMA burst of tile it
        {
            int s = it + 3;
            if (s < nIter) GEMM_ISSUE(s);
            cp_commit();
        }

        const unsigned stg = sbase + (unsigned)((it % STAGES) * STAGE_BYTES);

        unsigned bf[4][4];
#pragma unroll
        for (int ni = 0; ni < 4; ni++)
            ldsm_x4(bf[ni], stg + A_BYTES + b_ld + (unsigned)(ni * 8 * ROW_BYTES));

#pragma unroll
        for (int ks = 0; ks < 2; ks++) {
            unsigned af[4][4];
#pragma unroll
            for (int mi = 0; mi < 4; mi++)
                ldsm_x4(af[mi], stg + a_ld
                        + (unsigned)(mi * 16 * ROW_BYTES + (ks << 5)));
#pragma unroll
            for (int mi = 0; mi < 4; mi++)
#pragma unroll
                for (int ni = 0; ni < 4; ni++)
                    mma_f16(acc[mi][ni], af[mi], &bf[ni][ks << 1]);
        }
    }

#pragma unroll
    for (int mi = 0; mi < 4; mi++) {
        int r = row0 + (wm << 6) + (mi << 4) + grp;
#pragma unroll
        for (int ni = 0; ni < 4; ni++) {
            int c = col0 + (wn << 5) + (ni << 3) + (tig << 1);
            float2 bv = *(const float2*)&bias[c];
            float v00 = acc[mi][ni][0] + bv.x;
            float v01 = acc[mi][ni][1] + bv.y;
            float v10 = acc[mi][ni][2] + bv.x;
            float v11 = acc[mi][ni][3] + bv.y;
            if (RELU) {
                v00 = fmaxf(v00, 0.f); v01 = fmaxf(v01, 0.f);
                v10 = fmaxf(v10, 0.f); v11 = fmaxf(v11, 0.f);
            }
            if (OUT_HALF) {
                __half* Ch = (__half*)Cv;
                *(__half2*)&Ch[(size_t)r * N + c]       = __floats2half2_rn(v00, v01);
                *(__half2*)&Ch[(size_t)(r + 8) * N + c] = __floats2half2_rn(v10, v11);
            } else {
                float* Cf = (float*)Cv;
                float2 o0; o0.x = v00; o0.y = v01;
                float2 o1; o1.x = v10; o1.y = v11;
                *(float2*)&Cf[(size_t)r * N + c]       = o0;
                *(float2*)&Cf[(size_t)(r + 8) * N + c] = o1;
            }
        }
    }
}

// ---------------------------------------------------------------------------
// Tensor-core attention (unchanged from R11).  Grid = 1024 = (bg,head,qhalf).
// ---------------------------------------------------------------------------
#define ATTN_THREADS 256
#define QKV_STRIDE 1536
#define QP 72
#define ATTN_SMEM_BYTES ((128 + 256 + 256) * QP * 2)   // 92160

__global__ __launch_bounds__(ATTN_THREADS, 1)
void attn_mma(const __half* __restrict__ qkv, const void* __restrict__ maskp,
              __half* __restrict__ atted)
{
    extern __shared__ __half hs[];
    __half* Qs = hs;                 // 128 x QP
    __half* Ks = Qs + 128 * QP;      // 256 x QP
    __half* Vs = Ks + 256 * QP;      // 256 x QP
    __shared__ float mvals[256];

    const int bh   = blockIdx.x >> 1;
    const int qh   = blockIdx.x & 1;
    const int bg   = bh >> 4;
    const int h    = bh & 15;
    const int tid  = threadIdx.x;
    const int lane = tid & 31;
    const int w    = tid >> 5;
    const int lpar  = h >> 3;
    const int cbase = (h & 7) << 6;
    const int b = bg & 15;
    const int g = bg >> 4;
    const int h128 = qh << 7;

    unsigned word = ((const unsigned*)maskp)[tid];
    int is32 = __syncthreads_and(word <= 1u);

    const __half* base = qkv + (size_t)bg * 512 * QKV_STRIDE;

    for (int idx = tid; idx < 2048; idx += ATTN_THREADS) {
        int t  = idx >> 3;
        int d8 = (idx & 7) << 3;
        size_t off = (size_t)(2 * t + lpar) * QKV_STRIDE + cbase + d8;
        *(uint4*)&Ks[t * QP + d8] = *(const uint4*)(base + 512 + off);
        *(uint4*)&Vs[t * QP + d8] = *(const uint4*)(base + 1024 + off);
    }
    for (int idx = tid; idx < 1024; idx += ATTN_THREADS) {
        int t  = idx >> 3;
        int d8 = (idx & 7) << 3;
        size_t off = (size_t)(2 * (h128 + t) + lpar) * QKV_STRIDE + cbase + d8;
        *(uint4*)&Qs[t * QP + d8] = *(const uint4*)(base + off);
    }
    {
        int mv = is32 ? ((const int*)maskp)[b * 256 + tid]
                      : (int)((const unsigned char*)maskp)[b * 256 + tid];
        mvals[tid] = mv ? -1e9f : 0.0f;
    }
    __syncthreads();

    const unsigned qs0 = (unsigned)__cvta_generic_to_shared(Qs);
    const unsigned ks0 = (unsigned)__cvta_generic_to_shared(Ks);
    const unsigned vs0 = (unsigned)__cvta_generic_to_shared(Vs);

    const int lq = lane >> 2;
    const int lc = (lane & 3) << 1;
    const int qrow0 = w << 4;

    unsigned aq[4][4];
#pragma unroll
    for (int ks = 0; ks < 4; ks++) {
        unsigned addr = qs0 + (unsigned)(((qrow0 + (lane & 15)) * QP
                          + (ks << 4) + ((lane >> 4) << 3)) * 2);
        ldsm_x4(aq[ks], addr);
    }

    float acc[32][4];
#pragma unroll
    for (int nt = 0; nt < 32; nt++) {
        acc[nt][0] = 0.f; acc[nt][1] = 0.f; acc[nt][2] = 0.f; acc[nt][3] = 0.f;
        unsigned bk[2][4];
#pragma unroll
        for (int j = 0; j < 2; j++) {
            unsigned addr = ks0 + (unsigned)((((nt << 3) + (lane & 7)) * QP
                              + (j << 5) + ((lane >> 3) << 3)) * 2);
            ldsm_x4(bk[j], addr);
        }
        mma_f16(acc[nt], aq[0], &bk[0][0]);
        mma_f16(acc[nt], aq[1], &bk[0][2]);
        mma_f16(acc[nt], aq[2], &bk[1][0]);
        mma_f16(acc[nt], aq[3], &bk[1][2]);
    }

    const float scale = 0.125f;
    float m0 = -3.0e38f, m1 = -3.0e38f;
#pragma unroll
    for (int nt = 0; nt < 32; nt++) {
        float mv0 = mvals[(nt << 3) + lc];
        float mv1 = mvals[(nt << 3) + lc + 1];
        acc[nt][0] = acc[nt][0] * scale + mv0;
        acc[nt][1] = acc[nt][1] * scale + mv1;
        acc[nt][2] = acc[nt][2] * scale + mv0;
        acc[nt][3] = acc[nt][3] * scale + mv1;
        m0 = fmaxf(m0, fmaxf(acc[nt][0], acc[nt][1]));
        m1 = fmaxf(m1, fmaxf(acc[nt][2], acc[nt][3]));
    }
    m0 = fmaxf(m0, __shfl_xor_sync(0xffffffffu, m0, 1));
    m0 = fmaxf(m0, __shfl_xor_sync(0xffffffffu, m0, 2));
    m1 = fmaxf(m1, __shfl_xor_sync(0xffffffffu, m1, 1));
    m1 = fmaxf(m1, __shfl_xor_sync(0xffffffffu, m1, 2));

    float s0 = 0.f, s1 = 0.f;
#pragma unroll
    for (int nt = 0; nt < 32; nt++) {
        acc[nt][0] = __expf(acc[nt][0] - m0);
        acc[nt][1] = __expf(acc[nt][1] - m0);
        acc[nt][2] = __expf(acc[nt][2] - m1);
        acc[nt][3] = __expf(acc[nt][3] - m1);
        s0 += acc[nt][0] + acc[nt][1];
        s1 += acc[nt][2] + acc[nt][3];
    }
    s0 += __shfl_xor_sync(0xffffffffu, s0, 1);
    s0 += __shfl_xor_sync(0xffffffffu, s0, 2);
    s1 += __shfl_xor_sync(0xffffffffu, s1, 1);
    s1 += __shfl_xor_sync(0xffffffffu, s1, 2);
    const float inv0 = 1.f / s0;
    const float inv1 = 1.f / s1;

    float o[8][4];
#pragma unroll
    for (int dn = 0; dn < 8; dn++) {
        o[dn][0] = 0.f; o[dn][1] = 0.f; o[dn][2] = 0.f; o[dn][3] = 0.f;
    }
#pragma unroll
    for (int kt = 0; kt < 16; kt++) {
        unsigned pa[4];
        __half2 p0 = __floats2half2_rn(acc[2*kt][0],   acc[2*kt][1]);
        __half2 p1 = __floats2half2_rn(acc[2*kt][2],   acc[2*kt][3]);
        __half2 p2 = __floats2half2_rn(acc[2*kt+1][0], acc[2*kt+1][1]);
        __half2 p3 = __floats2half2_rn(acc[2*kt+1][2], acc[2*kt+1][3]);
        pa[0] = *(unsigned*)&p0; pa[1] = *(unsigned*)&p1;
        pa[2] = *(unsigned*)&p2; pa[3] = *(unsigned*)&p3;
#pragma unroll
        for (int p = 0; p < 4; p++) {
            unsigned bv[4];
            unsigned addr = vs0 + (unsigned)((((kt << 4) + ((lane >> 3) & 1) * 8
                              + (lane & 7)) * QP
                              + (p << 4) + ((lane >> 4) << 3)) * 2);
            ldsm_x4_t(bv, addr);
            mma_f16(o[2*p],     pa, &bv[0]);
            mma_f16(o[2*p + 1], pa, &bv[2]);
        }
    }

    const int t0 = h128 + qrow0 + lq;
#pragma unroll
    for (int dn = 0; dn < 8; dn++) {
        int d = (dn << 3) + lc;
        __half2 h0 = __floats2half2_rn(o[dn][0] * inv0, o[dn][1] * inv0);
        __half2 h1 = __floats2half2_rn(o[dn][2] * inv1, o[dn][3] * inv1);
        size_t ob0 = ((size_t)b * 512 + (2 * t0 + lpar)) * 1024
                   + (size_t)g * 512 + cbase + d;
        size_t ob1 = ((size_t)b * 512 + (2 * (t0 + 8) + lpar)) * 1024
                   + (size_t)g * 512 + cbase + d;
        *(__half2*)&atted[ob0] = h0;
        *(__half2*)&atted[ob1] = h1;
    }
}

// ---------------------------------------------------------------------------
// Residual-add + LayerNorm over rows of 1024. One block (256 thr) per row.
// ---------------------------------------------------------------------------
__global__ __launch_bounds__(256)
void add_ln_kernel(const float* __restrict__ res, const float* __restrict__ dlt,
                   const float* __restrict__ gamma, const float* __restrict__ beta,
                   float* __restrict__ out, __half* __restrict__ outh)
{
    __shared__ float red[8];
    __shared__ float s_mean, s_inv;
    const int row = blockIdx.x;
    const int tid = threadIdx.x;
    const size_t base = (size_t)row * 1024;
    const int c0 = tid << 2;

    float4 xr = *(const float4*)&res[base + c0];
    float4 xd = *(const float4*)&dlt[base + c0];
    float x[4] = { xr.x + xd.x, xr.y + xd.y, xr.z + xd.z, xr.w + xd.w };
    float s = x[0] + x[1] + x[2] + x[3];
#pragma unroll
    for (int o = 16; o; o >>= 1) s += __shfl_xor_sync(0xffffffffu, s, o);
    if ((tid & 31) == 0) red[tid >> 5] = s;
    __syncthreads();
    if (tid < 32) {
        float t = (tid < 8) ? red[tid] : 0.f;
#pragma unroll
        for (int o = 4; o; o >>= 1) t += __shfl_xor_sync(0xffffffffu, t, o);
        if (tid == 0) s_mean = t * (1.f / 1024.f);
    }
    __syncthreads();
    const float mean = s_mean;

    float vs = 0.f;
#pragma unroll
    for (int i = 0; i < 4; i++) { float d = x[i] - mean; vs += d * d; }
#pragma unroll
    for (int o = 16; o; o >>= 1) vs += __shfl_xor_sync(0xffffffffu, vs, o);
    if ((tid & 31) == 0) red[tid >> 5] = vs;
    __syncthreads();
    if (tid < 32) {
        float t = (tid < 8) ? red[tid] : 0.f;
#pragma unroll
        for (int o = 4; o; o >>= 1) t += __shfl_xor_sync(0xffffffffu, t, o);
        if (tid == 0) s_inv = rsqrtf(t * (1.f / 1024.f) + 1e-6f);
    }
    __syncthreads();
    const float inv = s_inv;

    float4 gm = *(const float4*)&gamma[c0];
    float4 bt = *(const float4*)&beta[c0];
    float4 o4;
    o4.x = (x[0] - mean) * inv * gm.x + bt.x;
    o4.y = (x[1] - mean) * inv * gm.y + bt.y;
    o4.z = (x[2] - mean) * inv * gm.z + bt.z;
    o4.w = (x[3] - mean) * inv * gm.w + bt.w;
    *(float4*)&out[base + c0] = o4;
    if (outh) {
        __half2 h0 = __floats2half2_rn(o4.x, o4.y);
        __half2 h1 = __floats2half2_rn(o4.z, o4.w);
        *(__half2*)&outh[base + c0]     = h0;
        *(__half2*)&outh[base + c0 + 2] = h1;
    }
}

// ---------------------------------------------------------------------------
// Launch.  8 kernels total.
// ---------------------------------------------------------------------------
extern "C" void kernel_launch(void* const* d_in, const int* in_sizes, int n_in,
                              void* d_out, int out_size)
{
    const float* y   = (const float*)d_in[0];
    const void*  msk = d_in[1];
    const float* Wv  = (const float*)d_in[2];
    const float* bv  = (const float*)d_in[3];
    const float* Wk  = (const float*)d_in[4];
    const float* bk  = (const float*)d_in[5];
    const float* Wq  = (const float*)d_in[6];
    const float* bq  = (const float*)d_in[7];
    const float* Wm  = (const float*)d_in[8];
    const float* bm  = (const float*)d_in[9];
    const float* W1  = (const float*)d_in[10];
    const float* b1  = (const float*)d_in[11];
    const float* W2  = (const float*)d_in[12];
    const float* b2  = (const float*)d_in[13];
    const float* g1  = (const float*)d_in[14];
    const float* be1 = (const float*)d_in[15];
    const float* g2  = (const float*)d_in[16];
    const float* be2 = (const float*)d_in[17];
    float* out = (float*)d_out;

    __half *yh, *wqkvT, *wmT, *w1T, *w2T, *qkv, *att, *y1h, *h1;
    float *bqkv, *mh, *y1, *ff;
    cudaGetSymbolAddress((void**)&yh,    g_yh);
    cudaGetSymbolAddress((void**)&wqkvT, g_wqkvT);
    cudaGetSymbolAddress((void**)&bqkv,  g_bqkv);
    cudaGetSymbolAddress((void**)&wmT,   g_wmT);
    cudaGetSymbolAddress((void**)&w1T,   g_w1T);
    cudaGetSymbolAddress((void**)&w2T,   g_w2T);
    cudaGetSymbolAddress((void**)&qkv,   g_qkv);
    cudaGetSymbolAddress((void**)&att,   g_att);
    cudaGetSymbolAddress((void**)&mh,    g_mh);
    cudaGetSymbolAddress((void**)&y1,    g_y1);
    cudaGetSymbolAddress((void**)&y1h,   g_y1h);
    cudaGetSymbolAddress((void**)&h1,    g_h1);
    cudaGetSymbolAddress((void**)&ff,    g_ff);

    cudaFuncSetAttribute(attn_mma,
                         cudaFuncAttributeMaxDynamicSharedMemorySize, ATTN_SMEM_BYTES);
    cudaFuncSetAttribute(hgemm<true,  false, true >,
                         cudaFuncAttributeMaxDynamicSharedMemorySize, GEMM_SMEM_BYTES);
    cudaFuncSetAttribute(hgemm<false, false, false>,
                         cudaFuncAttributeMaxDynamicSharedMemorySize, GEMM_SMEM_BYTES);
    cudaFuncSetAttribute(hgemm<false, true,  true >,
                         cudaFuncAttributeMaxDynamicSharedMemorySize, GEMM_SMEM_BYTES);

    dim3 blk(256);

    // 1) fused pre-pass
    prep<<<7937, blk>>>(y, yh, Wq, Wk, Wv, wqkvT, Wm, wmT, W1, w1T, W2, w2T,
                        bq, bk, bv, bqkv);

    // 2) Fused QKV: (16384,1536) = gather(yh) @ Wqkv + bqkv -> half
    hgemm<true,  false, true ><<<dim3(12, 128), blk, GEMM_SMEM_BYTES>>>(yh, wqkvT, bqkv, qkv, 16384, 1536, 512);

    // 3) Tensor-core attention -> att (half, B,L,H layout)
    attn_mma<<<1024, ATTN_THREADS, ATTN_SMEM_BYTES>>>(qkv, msk, att);

    // 4) Merge: (8192,1024) @ Wm + bm -> fp32
    hgemm<false, false, false><<<dim3(8, 64), blk, GEMM_SMEM_BYTES>>>(att, wmT, bm, mh, 8192, 1024, 1024);

    // 5) y1 = LN(y + merge): fp32 (residual) + half (FFN1 input)
    add_ln_kernel<<<8192, blk>>>(y, mh, g1, be1, y1, y1h);

    // 6) FFN1: (8192,1024) @ W1 + b1, relu -> half
    hgemm<false, true,  true ><<<dim3(32, 64), blk, GEMM_SMEM_BYTES>>>(y1h, w1T, b1, h1, 8192, 4096, 1024);

    // 7) FFN2: (16384,2048) @ W2 + b2 -> fp32
    hgemm<false, false, false><<<dim3(4, 128), blk, GEMM_SMEM_BYTES>>>(h1, w2T, b2, ff, 16384, 512, 2048);

    // 8) out = LN(y1 + ff), full fp32
    add_ln_kernel<<<8192, blk>>>(y1, ff, g2, be2, out, (__half*)0);
}

// round 13
// speedup vs baseline: 1.0638x; 1.0638x over previous
#include <cuda_runtime.h>
#include <cuda_fp16.h>
#include <math.h>
#include <stdint.h>

// ---------------------------------------------------------------------------
// Problem constants: B=16, L=512, H=1024, G=2, NH=16, DH=64, FF=4096,
//                    DM=512, LG=256
// ---------------------------------------------------------------------------

// Scratch (device globals; allocation inside kernel_launch is forbidden)
__device__ __half g_yh   [16u*512u*1024u];
__device__ __half g_wqkvT[1536u*512u];
__device__ float  g_bqkv [1536u];
__device__ __half g_wmT  [1024u*1024u];
__device__ __half g_w1T  [4096u*1024u];
__device__ __half g_w2T  [512u*2048u];
__device__ __half g_qkv  [16384u*1536u];
__device__ __half g_att  [16u*512u*1024u];
__device__ float  g_mh   [16u*512u*1024u];
__device__ float  g_y1   [16u*512u*1024u];
__device__ __half g_y1h  [16u*512u*1024u];
__device__ __half g_h1   [8192u*4096u];
__device__ float  g_ff   [16u*512u*1024u];

// ---------------------------------------------------------------------------
// Helpers
// ---------------------------------------------------------------------------
__device__ __forceinline__ void mma_f16(float* d, const unsigned* a, const unsigned* b) {
    asm volatile(
        "mma.sync.aligned.m16n8k16.row.col.f32.f16.f16.f32 "
        "{%0,%1,%2,%3}, {%4,%5,%6,%7}, {%8,%9}, {%0,%1,%2,%3};\n"
        : "+f"(d[0]), "+f"(d[1]), "+f"(d[2]), "+f"(d[3])
        : "r"(a[0]), "r"(a[1]), "r"(a[2]), "r"(a[3]), "r"(b[0]), "r"(b[1]));
}

__device__ __forceinline__ void ldsm_x4(unsigned* r, unsigned a) {
    asm volatile("ldmatrix.sync.aligned.m8n8.x4.shared.b16 {%0,%1,%2,%3}, [%4];"
        : "=r"(r[0]), "=r"(r[1]), "=r"(r[2]), "=r"(r[3]) : "r"(a));
}
__device__ __forceinline__ void ldsm_x4_t(unsigned* r, unsigned a) {
    asm volatile("ldmatrix.sync.aligned.m8n8.x4.trans.shared.b16 {%0,%1,%2,%3}, [%4];"
        : "=r"(r[0]), "=r"(r[1]), "=r"(r[2]), "=r"(r[3]) : "r"(a));
}

__device__ __forceinline__ void cp16(unsigned dst, const void* src) {
    asm volatile("cp.async.cg.shared.global [%0], [%1], 16;\n" :: "r"(dst), "l"(src));
}
__device__ __forceinline__ void cp_commit() {
    asm volatile("cp.async.commit_group;\n" ::);
}
template<int N>
__device__ __forceinline__ void cp_wait() {
    asm volatile("cp.async.wait_group %0;\n" :: "n"(N));
}

// ---------------------------------------------------------------------------
// Fused pre-pass (unchanged): weight transposes (+half), y->half, bias pack.
// ---------------------------------------------------------------------------
__device__ __forceinline__ void transp_tile(const float* __restrict__ in,
                                            __half* __restrict__ out,
                                            int K, int N, int nb, int kb,
                                            float (*t)[33], int tid)
{
    int tx = tid & 31, ty = tid >> 5;
#pragma unroll
    for (int i = 0; i < 32; i += 8)
        t[ty + i][tx] = in[(size_t)(kb + ty + i) * N + nb + tx];
    __syncthreads();
#pragma unroll
    for (int i = 0; i < 32; i += 8)
        out[(size_t)(nb + ty + i) * K + kb + tx] = __float2half(t[tx][ty + i]);
}

__global__ __launch_bounds__(256)
void prep(const float* __restrict__ y, __half* __restrict__ yh,
          const float* __restrict__ Wq, const float* __restrict__ Wk,
          const float* __restrict__ Wv, __half* __restrict__ wqkvT,
          const float* __restrict__ Wm, __half* __restrict__ wmT,
          const float* __restrict__ W1, __half* __restrict__ w1T,
          const float* __restrict__ W2, __half* __restrict__ w2T,
          const float* __restrict__ bq, const float* __restrict__ bk,
          const float* __restrict__ bv, float* __restrict__ bqkv)
{
    __shared__ float t[32][33];
    const int bid = blockIdx.x;
    const int tid = threadIdx.x;

    if (bid < 768) {
        int nbt = bid % 48, kbt = bid / 48;
        int nb = nbt << 5, kb = kbt << 5;
        const float* src = (nb < 512) ? Wq : (nb < 1024) ? Wk : Wv;
        int nloc = nb & 511;
        int tx = tid & 31, ty = tid >> 5;
#pragma unroll
        for (int i = 0; i < 32; i += 8)
            t[ty + i][tx] = src[(size_t)(kb + ty + i) * 512 + nloc + tx];
        __syncthreads();
#pragma unroll
        for (int i = 0; i < 32; i += 8)
            wqkvT[(size_t)(nb + ty + i) * 512 + kb + tx] = __float2half(t[tx][ty + i]);
    } else if (bid < 1792) {
        int r = bid - 768;
        transp_tile(Wm, wmT, 1024, 1024, (r % 32) << 5, (r / 32) << 5, t, tid);
    } else if (bid < 5888) {
        int r = bid - 1792;
        transp_tile(W1, w1T, 1024, 4096, (r % 128) << 5, (r / 128) << 5, t, tid);
    } else if (bid < 6912) {
        int r = bid - 5888;
        transp_tile(W2, w2T, 2048, 512, (r % 16) << 5, (r / 16) << 5, t, tid);
    } else if (bid < 7936) {
        size_t base = (size_t)(bid - 6912) * 8192 + (tid << 2);
#pragma unroll
        for (int j = 0; j < 8; j++) {
            size_t idx = base + (size_t)j * 1024;
            float4 v = *(const float4*)&y[idx];
            __half2 h0 = __floats2half2_rn(v.x, v.y);
            __half2 h1 = __floats2half2_rn(v.z, v.w);
            *(__half2*)&yh[idx]     = h0;
            *(__half2*)&yh[idx + 2] = h1;
        }
    } else {
#pragma unroll
        for (int j = 0; j < 6; j++) {
            int i = tid + (j << 8);
            int s = i >> 9, c = i & 511;
            const float* bs = (s == 0) ? bq : (s == 1) ? bk : bv;
            bqkv[i] = bs[c];
        }
    }
}

// ---------------------------------------------------------------------------
// fp16 tensor-core GEMM — EXACT R8 config (best measured): 128x128 tile,
// K-step 32, 256 thr, 8 warps 2Mx4N, warp tile 64x32, ldmatrix.x4,
// 3-stage cp.async (issue after MMA), 60KB smem -> 2 CTAs/SM.
// ---------------------------------------------------------------------------
#define STAGES 3
#define ROW_BYTES 80
#define A_BYTES (128 * ROW_BYTES)
#define STAGE_BYTES (2 * A_BYTES)
#define GEMM_SMEM_BYTES (STAGES * STAGE_BYTES)  // 61440

#define GEMM_ISSUE(s_) do {                                                   \
    int ko_ = (s_) << 5;                                                      \
    unsigned sb_ = sbase + (unsigned)(((s_) % STAGES) * STAGE_BYTES);         \
    _Pragma("unroll")                                                         \
    for (int i_ = 0; i_ < 2; i_++) cp16(sb_ + a_sm[i_], a_gm[i_] + ko_);      \
    _Pragma("unroll")                                                         \
    for (int i_ = 0; i_ < 2; i_++)                                            \
        cp16(sb_ + A_BYTES + b_sm[i_], b_gm[i_] + ko_);                       \
} while (0)

template<bool GATHER_A, bool RELU, bool OUT_HALF>
__global__ __launch_bounds__(256, 2)
void hgemm(const __half* __restrict__ A, const __half* __restrict__ BT,
           const float* __restrict__ bias, void* __restrict__ Cv,
           int M, int N, int K)
{
    extern __shared__ unsigned char dsm[];
    const unsigned sbase = (unsigned)__cvta_generic_to_shared(dsm);

    const int tid  = threadIdx.x;
    const int row0 = blockIdx.y << 7;
    const int col0 = blockIdx.x << 7;
    const int lane = tid & 31;
    const int w    = tid >> 5;
    const int wm   = w & 1;
    const int wn   = w >> 1;
    const int tig  = lane & 3;
    const int grp  = lane >> 2;

    unsigned a_sm[2], b_sm[2];
    const __half* a_gm[2];
    const __half* b_gm[2];
#pragma unroll
    for (int i = 0; i < 2; i++) {
        int ci = tid + (i << 8);
        int r  = ci >> 2;
        int kc = (ci & 3) << 3;
        a_sm[i] = (unsigned)(r * ROW_BYTES + (kc << 1));
        b_sm[i] = a_sm[i];
        int grow = row0 + r;
        if (GATHER_A) {
            int bg = grow >> 9, l = grow & 511;
            int b  = bg & 15,  g = bg >> 4;
            a_gm[i] = A + (((size_t)b * 512 + l) * 1024 + (size_t)g * 512) + kc;
        } else {
            a_gm[i] = A + (size_t)grow * (size_t)K + kc;
        }
        b_gm[i] = BT + (size_t)(col0 + r) * (size_t)K + kc;
    }

    const unsigned a_ld = (unsigned)(((wm << 6) + (lane & 15)) * ROW_BYTES
                                     + (((lane >> 4) << 3) << 1));
    const unsigned b_ld = (unsigned)((((wn << 5) + (lane & 7)) * ROW_BYTES)
                                     + ((((lane >> 3) & 3) << 3) << 1));

    float acc[4][4][4];
#pragma unroll
    for (int mi = 0; mi < 4; mi++)
#pragma unroll
        for (int ni = 0; ni < 4; ni++)
#pragma unroll
            for (int j = 0; j < 4; j++) acc[mi][ni][j] = 0.f;

    GEMM_ISSUE(0); cp_commit();
    GEMM_ISSUE(1); cp_commit();

    const int nIter = K >> 5;
    for (int it = 0; it < nIter; ++it) {
        cp_wait<1>();
        __syncthreads();

        const unsigned stg = sbase + (unsigned)((it % STAGES) * STAGE_BYTES);

        unsigned bf[4][4];
#pragma unroll
        for (int ni = 0; ni < 4; ni++)
            ldsm_x4(bf[ni], stg + A_BYTES + b_ld + (unsigned)(ni * 8 * ROW_BYTES));

#pragma unroll
        for (int ks = 0; ks < 2; ks++) {
            unsigned af[4][4];
#pragma unroll
            for (int mi = 0; mi < 4; mi++)
                ldsm_x4(af[mi], stg + a_ld
                        + (unsigned)(mi * 16 * ROW_BYTES + (ks << 5)));
#pragma unroll
            for (int mi = 0; mi < 4; mi++)
#pragma unroll
                for (int ni = 0; ni < 4; ni++)
                    mma_f16(acc[mi][ni], af[mi], &bf[ni][ks << 1]);
        }

        int s = it + 2;
        if (s < nIter) GEMM_ISSUE(s);
        cp_commit();
    }

#pragma unroll
    for (int mi = 0; mi < 4; mi++) {
        int r = row0 + (wm << 6) + (mi << 4) + grp;
#pragma unroll
        for (int ni = 0; ni < 4; ni++) {
            int c = col0 + (wn << 5) + (ni << 3) + (tig << 1);
            float2 bv = *(const float2*)&bias[c];
            float v00 = acc[mi][ni][0] + bv.x;
            float v01 = acc[mi][ni][1] + bv.y;
            float v10 = acc[mi][ni][2] + bv.x;
            float v11 = acc[mi][ni][3] + bv.y;
            if (RELU) {
                v00 = fmaxf(v00, 0.f); v01 = fmaxf(v01, 0.f);
                v10 = fmaxf(v10, 0.f); v11 = fmaxf(v11, 0.f);
            }
            if (OUT_HALF) {
                __half* Ch = (__half*)Cv;
                *(__half2*)&Ch[(size_t)r * N + c]       = __floats2half2_rn(v00, v01);
                *(__half2*)&Ch[(size_t)(r + 8) * N + c] = __floats2half2_rn(v10, v11);
            } else {
                float* Cf = (float*)Cv;
                float2 o0; o0.x = v00; o0.y = v01;
                float2 o1; o1.x = v10; o1.y = v11;
                *(float2*)&Cf[(size_t)r * N + c]       = o0;
                *(float2*)&Cf[(size_t)(r + 8) * N + c] = o1;
            }
        }
    }
}

// ---------------------------------------------------------------------------
// Tensor-core attention, flash 2-chunk over keys to halve registers
// (acc[16][4] instead of [32][4]) -> fits 128-reg cap -> 2 CTAs/SM.
// Grid = 1024 = (bg, head, q-half), 256 threads, 8 warps x 16 q rows.
// Running max/sum rescale across the two 128-key chunks; 1/sum folded
// into the epilogue.  P reused as A-fragments for PV (ldmatrix.x4.trans).
// ---------------------------------------------------------------------------
#define ATTN_THREADS 256
#define QKV_STRIDE 1536
#define QP 72
#define ATTN_SMEM_BYTES ((128 + 256 + 256) * QP * 2)   // 92160

__global__ __launch_bounds__(ATTN_THREADS, 2)
void attn_mma(const __half* __restrict__ qkv, const void* __restrict__ maskp,
              __half* __restrict__ atted)
{
    extern __shared__ __half hs[];
    __half* Qs = hs;                 // 128 x QP
    __half* Ks = Qs + 128 * QP;      // 256 x QP
    __half* Vs = Ks + 256 * QP;      // 256 x QP
    __shared__ float mvals[256];

    const int bh   = blockIdx.x >> 1;
    const int qh   = blockIdx.x & 1;
    const int bg   = bh >> 4;
    const int h    = bh & 15;
    const int tid  = threadIdx.x;
    const int lane = tid & 31;
    const int w    = tid >> 5;
    const int lpar  = h >> 3;
    const int cbase = (h & 7) << 6;
    const int b = bg & 15;
    const int g = bg >> 4;
    const int h128 = qh << 7;

    unsigned word = ((const unsigned*)maskp)[tid];
    int is32 = __syncthreads_and(word <= 1u);

    const __half* base = qkv + (size_t)bg * 512 * QKV_STRIDE;

    for (int idx = tid; idx < 2048; idx += ATTN_THREADS) {
        int t  = idx >> 3;
        int d8 = (idx & 7) << 3;
        size_t off = (size_t)(2 * t + lpar) * QKV_STRIDE + cbase + d8;
        *(uint4*)&Ks[t * QP + d8] = *(const uint4*)(base + 512 + off);
        *(uint4*)&Vs[t * QP + d8] = *(const uint4*)(base + 1024 + off);
    }
    for (int idx = tid; idx < 1024; idx += ATTN_THREADS) {
        int t  = idx >> 3;
        int d8 = (idx & 7) << 3;
        size_t off = (size_t)(2 * (h128 + t) + lpar) * QKV_STRIDE + cbase + d8;
        *(uint4*)&Qs[t * QP + d8] = *(const uint4*)(base + off);
    }
    {
        int mv = is32 ? ((const int*)maskp)[b * 256 + tid]
                      : (int)((const unsigned char*)maskp)[b * 256 + tid];
        mvals[tid] = mv ? -1e9f : 0.0f;
    }
    __syncthreads();

    const unsigned qs0 = (unsigned)__cvta_generic_to_shared(Qs);
    const unsigned ks0 = (unsigned)__cvta_generic_to_shared(Ks);
    const unsigned vs0 = (unsigned)__cvta_generic_to_shared(Vs);

    const int lq = lane >> 2;
    const int lc = (lane & 3) << 1;
    const int qrow0 = w << 4;

    // A fragments of Q (4 k-steps), loaded once
    unsigned aq[4][4];
#pragma unroll
    for (int ks = 0; ks < 4; ks++) {
        unsigned addr = qs0 + (unsigned)(((qrow0 + (lane & 15)) * QP
                          + (ks << 4) + ((lane >> 4) << 3)) * 2);
        ldsm_x4(aq[ks], addr);
    }

    const float scale = 0.125f;
    float m0 = -3.0e38f, m1 = -3.0e38f;   // running max (rows lq, lq+8)
    float s0 = 0.f, s1 = 0.f;             // running sum
    float o[8][4];
#pragma unroll
    for (int dn = 0; dn < 8; dn++) {
        o[dn][0] = 0.f; o[dn][1] = 0.f; o[dn][2] = 0.f; o[dn][3] = 0.f;
    }

#pragma unroll 1
    for (int c = 0; c < 2; c++) {
        const int kbase = c << 7;        // key chunk offset (rows in Ks/Vs)

        // --- S chunk: 16 n-tiles x 4 f32 ---
        float acc[16][4];
#pragma unroll
        for (int nt = 0; nt < 16; nt++) {
            acc[nt][0] = 0.f; acc[nt][1] = 0.f; acc[nt][2] = 0.f; acc[nt][3] = 0.f;
            unsigned bk[2][4];
#pragma unroll
            for (int j = 0; j < 2; j++) {
                unsigned addr = ks0 + (unsigned)(((kbase + (nt << 3) + (lane & 7)) * QP
                                  + (j << 5) + ((lane >> 3) << 3)) * 2);
                ldsm_x4(bk[j], addr);
            }
            mma_f16(acc[nt], aq[0], &bk[0][0]);
            mma_f16(acc[nt], aq[1], &bk[0][2]);
            mma_f16(acc[nt], aq[2], &bk[1][0]);
            mma_f16(acc[nt], aq[3], &bk[1][2]);
        }

        // --- scale + mask + chunk max ---
        float cm0 = -3.0e38f, cm1 = -3.0e38f;
#pragma unroll
        for (int nt = 0; nt < 16; nt++) {
            float mv0 = mvals[kbase + (nt << 3) + lc];
            float mv1 = mvals[kbase + (nt << 3) + lc + 1];
            acc[nt][0] = acc[nt][0] * scale + mv0;
            acc[nt][1] = acc[nt][1] * scale + mv1;
            acc[nt][2] = acc[nt][2] * scale + mv0;
            acc[nt][3] = acc[nt][3] * scale + mv1;
            cm0 = fmaxf(cm0, fmaxf(acc[nt][0], acc[nt][1]));
            cm1 = fmaxf(cm1, fmaxf(acc[nt][2], acc[nt][3]));
        }
        cm0 = fmaxf(cm0, __shfl_xor_sync(0xffffffffu, cm0, 1));
        cm0 = fmaxf(cm0, __shfl_xor_sync(0xffffffffu, cm0, 2));
        cm1 = fmaxf(cm1, __shfl_xor_sync(0xffffffffu, cm1, 1));
        cm1 = fmaxf(cm1, __shfl_xor_sync(0xffffffffu, cm1, 2));

        // --- running rescale ---
        float nm0 = fmaxf(m0, cm0);
        float nm1 = fmaxf(m1, cm1);
        float f0 = __expf(m0 - nm0);      // 0 on first chunk (m0 = -3e38)
        float f1 = __expf(m1 - nm1);
        m0 = nm0; m1 = nm1;
        s0 *= f0; s1 *= f1;
#pragma unroll
        for (int dn = 0; dn < 8; dn++) {
            o[dn][0] *= f0; o[dn][1] *= f0;
            o[dn][2] *= f1; o[dn][3] *= f1;
        }

        // --- exp + chunk sums ---
        float cs0 = 0.f, cs1 = 0.f;
#pragma unroll
        for (int nt = 0; nt < 16; nt++) {
            acc[nt][0] = __expf(acc[nt][0] - m0);
            acc[nt][1] = __expf(acc[nt][1] - m0);
            acc[nt][2] = __expf(acc[nt][2] - m1);
            acc[nt][3] = __expf(acc[nt][3] - m1);
            cs0 += acc[nt][0] + acc[nt][1];
            cs1 += acc[nt][2] + acc[nt][3];
        }
        s0 += cs0;
        s1 += cs1;

        // --- O += P V (chunk) ---
#pragma unroll
        for (int kt = 0; kt < 8; kt++) {
            unsigned pa[4];
            __half2 p0 = __floats2half2_rn(acc[2*kt][0],   acc[2*kt][1]);
            __half2 p1 = __floats2half2_rn(acc[2*kt][2],   acc[2*kt][3]);
            __half2 p2 = __floats2half2_rn(acc[2*kt+1][0], acc[2*kt+1][1]);
            __half2 p3 = __floats2half2_rn(acc[2*kt+1][2], acc[2*kt+1][3]);
            pa[0] = *(unsigned*)&p0; pa[1] = *(unsigned*)&p1;
            pa[2] = *(unsigned*)&p2; pa[3] = *(unsigned*)&p3;
#pragma unroll
            for (int p = 0; p < 4; p++) {
                unsigned bv[4];
                unsigned addr = vs0 + (unsigned)(((kbase + (kt << 4)
                                  + ((lane >> 3) & 1) * 8 + (lane & 7)) * QP
                                  + (p << 4) + ((lane >> 4) << 3)) * 2);
                ldsm_x4_t(bv, addr);
                mma_f16(o[2*p],     pa, &bv[0]);
                mma_f16(o[2*p + 1], pa, &bv[2]);
            }
        }
    }

    // quad-reduce running sums (each lane-quad shares the row)
    s0 += __shfl_xor_sync(0xffffffffu, s0, 1);
    s0 += __shfl_xor_sync(0xffffffffu, s0, 2);
    s1 += __shfl_xor_sync(0xffffffffu, s1, 1);
    s1 += __shfl_xor_sync(0xffffffffu, s1, 2);
    const float inv0 = 1.f / s0;
    const float inv1 = 1.f / s1;

    const int t0 = h128 + qrow0 + lq;
#pragma unroll
    for (int dn = 0; dn < 8; dn++) {
        int d = (dn << 3) + lc;
        __half2 h0 = __floats2half2_rn(o[dn][0] * inv0, o[dn][1] * inv0);
        __half2 h1 = __floats2half2_rn(o[dn][2] * inv1, o[dn][3] * inv1);
        size_t ob0 = ((size_t)b * 512 + (2 * t0 + lpar)) * 1024
                   + (size_t)g * 512 + cbase + d;
        size_t ob1 = ((size_t)b * 512 + (2 * (t0 + 8) + lpar)) * 1024
                   + (size_t)g * 512 + cbase + d;
        *(__half2*)&atted[ob0] = h0;
        *(__half2*)&atted[ob1] = h1;
    }
}

// Wait: sums must be reduced across the quad BEFORE being used per chunk?
// No — s0/s1 accumulate per-lane partial sums (each lane owns 2 columns per
// nt); the quad reduction at the end yields the full row sum, and the
// rescale factors f0/f1 depend only on m0/m1 which ARE quad-reduced per
// chunk.  o also accumulates unnormalized, so end-only sum reduction is
// exact.  (comment retained as proof sketch)

// ---------------------------------------------------------------------------
// Residual-add + LayerNorm over rows of 1024. One block (256 thr) per row.
// ---------------------------------------------------------------------------
__global__ __launch_bounds__(256)
void add_ln_kernel(const float* __restrict__ res, const float* __restrict__ dlt,
                   const float* __restrict__ gamma, const float* __restrict__ beta,
                   float* __restrict__ out, __half* __restrict__ outh)
{
    __shared__ float red[8];
    __shared__ float s_mean, s_inv;
    const int row = blockIdx.x;
    const int tid = threadIdx.x;
    const size_t base = (size_t)row * 1024;
    const int c0 = tid << 2;

    float4 xr = *(const float4*)&res[base + c0];
    float4 xd = *(const float4*)&dlt[base + c0];
    float x[4] = { xr.x + xd.x, xr.y + xd.y, xr.z + xd.z, xr.w + xd.w };
    float s = x[0] + x[1] + x[2] + x[3];
#pragma unroll
    for (int o = 16; o; o >>= 1) s += __shfl_xor_sync(0xffffffffu, s, o);
    if ((tid & 31) == 0) red[tid >> 5] = s;
    __syncthreads();
    if (tid < 32) {
        float t = (tid < 8) ? red[tid] : 0.f;
#pragma unroll
        for (int o = 4; o; o >>= 1) t += __shfl_xor_sync(0xffffffffu, t, o);
        if (tid == 0) s_mean = t * (1.f / 1024.f);
    }
    __syncthreads();
    const float mean = s_mean;

    float vs = 0.f;
#pragma unroll
    for (int i = 0; i < 4; i++) { float d = x[i] - mean; vs += d * d; }
#pragma unroll
    for (int o = 16; o; o >>= 1) vs += __shfl_xor_sync(0xffffffffu, vs, o);
    if ((tid & 31) == 0) red[tid >> 5] = vs;
    __syncthreads();
    if (tid < 32) {
        float t = (tid < 8) ? red[tid] : 0.f;
#pragma unroll
        for (int o = 4; o; o >>= 1) t += __shfl_xor_sync(0xffffffffu, t, o);
        if (tid == 0) s_inv = rsqrtf(t * (1.f / 1024.f) + 1e-6f);
    }
    __syncthreads();
    const float inv = s_inv;

    float4 gm = *(const float4*)&gamma[c0];
    float4 bt = *(const float4*)&beta[c0];
    float4 o4;
    o4.x = (x[0] - mean) * inv * gm.x + bt.x;
    o4.y = (x[1] - mean) * inv * gm.y + bt.y;
    o4.z = (x[2] - mean) * inv * gm.z + bt.z;
    o4.w = (x[3] - mean) * inv * gm.w + bt.w;
    *(float4*)&out[base + c0] = o4;
    if (outh) {
        __half2 h0 = __floats2half2_rn(o4.x, o4.y);
        __half2 h1 = __floats2half2_rn(o4.z, o4.w);
        *(__half2*)&outh[base + c0]     = h0;
        *(__half2*)&outh[base + c0 + 2] = h1;
    }
}

// ---------------------------------------------------------------------------
// Launch.  8 kernels total.
// ---------------------------------------------------------------------------
extern "C" void kernel_launch(void* const* d_in, const int* in_sizes, int n_in,
                              void* d_out, int out_size)
{
    const float* y   = (const float*)d_in[0];
    const void*  msk = d_in[1];
    const float* Wv  = (const float*)d_in[2];
    const float* bv  = (const float*)d_in[3];
    const float* Wk  = (const float*)d_in[4];
    const float* bk  = (const float*)d_in[5];
    const float* Wq  = (const float*)d_in[6];
    const float* bq  = (const float*)d_in[7];
    const float* Wm  = (const float*)d_in[8];
    const float* bm  = (const float*)d_in[9];
    const float* W1  = (const float*)d_in[10];
    const float* b1  = (const float*)d_in[11];
    const float* W2  = (const float*)d_in[12];
    const float* b2  = (const float*)d_in[13];
    const float* g1  = (const float*)d_in[14];
    const float* be1 = (const float*)d_in[15];
    const float* g2  = (const float*)d_in[16];
    const float* be2 = (const float*)d_in[17];
    float* out = (float*)d_out;

    __half *yh, *wqkvT, *wmT, *w1T, *w2T, *qkv, *att, *y1h, *h1;
    float *bqkv, *mh, *y1, *ff;
    cudaGetSymbolAddress((void**)&yh,    g_yh);
    cudaGetSymbolAddress((void**)&wqkvT, g_wqkvT);
    cudaGetSymbolAddress((void**)&bqkv,  g_bqkv);
    cudaGetSymbolAddress((void**)&wmT,   g_wmT);
    cudaGetSymbolAddress((void**)&w1T,   g_w1T);
    cudaGetSymbolAddress((void**)&w2T,   g_w2T);
    cudaGetSymbolAddress((void**)&qkv,   g_qkv);
    cudaGetSymbolAddress((void**)&att,   g_att);
    cudaGetSymbolAddress((void**)&mh,    g_mh);
    cudaGetSymbolAddress((void**)&y1,    g_y1);
    cudaGetSymbolAddress((void**)&y1h,   g_y1h);
    cudaGetSymbolAddress((void**)&h1,    g_h1);
    cudaGetSymbolAddress((void**)&ff,    g_ff);

    cudaFuncSetAttribute(attn_mma,
                         cudaFuncAttributeMaxDynamicSharedMemorySize, ATTN_SMEM_BYTES);
    cudaFuncSetAttribute(hgemm<true,  false, true >,
                         cudaFuncAttributeMaxDynamicSharedMemorySize, GEMM_SMEM_BYTES);
    cudaFuncSetAttribute(hgemm<false, false, false>,
                         cudaFuncAttributeMaxDynamicSharedMemorySize, GEMM_SMEM_BYTES);
    cudaFuncSetAttribute(hgemm<false, true,  true >,
                         cudaFuncAttributeMaxDynamicSharedMemorySize, GEMM_SMEM_BYTES);

    dim3 blk(256);

    // 1) fused pre-pass
    prep<<<7937, blk>>>(y, yh, Wq, Wk, Wv, wqkvT, Wm, wmT, W1, w1T, W2, w2T,
                        bq, bk, bv, bqkv);

    // 2) Fused QKV: (16384,1536) = gather(yh) @ Wqkv + bqkv -> half
    hgemm<true,  false, true ><<<dim3(12, 128), blk, GEMM_SMEM_BYTES>>>(yh, wqkvT, bqkv, qkv, 16384, 1536, 512);

    // 3) Flash tensor-core attention -> att (half, B,L,H layout)
    attn_mma<<<1024, ATTN_THREADS, ATTN_SMEM_BYTES>>>(qkv, msk, att);

    // 4) Merge: (8192,1024) @ Wm + bm -> fp32
    hgemm<false, false, false><<<dim3(8, 64), blk, GEMM_SMEM_BYTES>>>(att, wmT, bm, mh, 8192, 1024, 1024);

    // 5) y1 = LN(y + merge): fp32 (residual) + half (FFN1 input)
    add_ln_kernel<<<8192, blk>>>(y, mh, g1, be1, y1, y1h);

    // 6) FFN1: (8192,1024) @ W1 + b1, relu -> half
    hgemm<false, true,  true ><<<dim3(32, 64), blk, GEMM_SMEM_BYTES>>>(y1h, w1T, b1, h1, 8192, 4096, 1024);

    // 7) FFN2: (16384,2048) @ W2 + b2 -> fp32
    hgemm<false, false, false><<<dim3(4, 128), blk, GEMM_SMEM_BYTES>>>(h1, w2T, b2, ff, 16384, 512, 2048);

    // 8) out = LN(y1 + ff), full fp32
    add_ln_kernel<<<8192, blk>>>(y1, ff, g2, be2, out, (__half*)0);
}

// round 14
// speedup vs baseline: 1.0787x; 1.0139x over previous
#include <cuda_runtime.h>
#include <cuda_fp16.h>
#include <math.h>
#include <stdint.h>

// ---------------------------------------------------------------------------
// Problem constants: B=16, L=512, H=1024, G=2, NH=16, DH=64, FF=4096,
//                    DM=512, LG=256
// ---------------------------------------------------------------------------

// Scratch (device globals; allocation inside kernel_launch is forbidden)
__device__ __half g_yh   [16u*512u*1024u];
__device__ __half g_wqkvT[1536u*512u];
__device__ float  g_bqkv [1536u];
__device__ __half g_wmT  [1024u*1024u];
__device__ __half g_w1T  [4096u*1024u];
__device__ __half g_w2T  [512u*2048u];
__device__ __half g_qkv  [16384u*1536u];
__device__ __half g_att  [16u*512u*1024u];
__device__ float  g_mh   [16u*512u*1024u];
__device__ float  g_y1   [16u*512u*1024u];
__device__ __half g_y1h  [16u*512u*1024u];
__device__ __half g_h1   [8192u*4096u];
__device__ float  g_ff   [16u*512u*1024u];

// ---------------------------------------------------------------------------
// Helpers
// ---------------------------------------------------------------------------
__device__ __forceinline__ void mma_f16(float* d, const unsigned* a, const unsigned* b) {
    asm volatile(
        "mma.sync.aligned.m16n8k16.row.col.f32.f16.f16.f32 "
        "{%0,%1,%2,%3}, {%4,%5,%6,%7}, {%8,%9}, {%0,%1,%2,%3};\n"
        : "+f"(d[0]), "+f"(d[1]), "+f"(d[2]), "+f"(d[3])
        : "r"(a[0]), "r"(a[1]), "r"(a[2]), "r"(a[3]), "r"(b[0]), "r"(b[1]));
}

__device__ __forceinline__ void ldsm_x4(unsigned* r, unsigned a) {
    asm volatile("ldmatrix.sync.aligned.m8n8.x4.shared.b16 {%0,%1,%2,%3}, [%4];"
        : "=r"(r[0]), "=r"(r[1]), "=r"(r[2]), "=r"(r[3]) : "r"(a));
}
__device__ __forceinline__ void ldsm_x4_t(unsigned* r, unsigned a) {
    asm volatile("ldmatrix.sync.aligned.m8n8.x4.trans.shared.b16 {%0,%1,%2,%3}, [%4];"
        : "=r"(r[0]), "=r"(r[1]), "=r"(r[2]), "=r"(r[3]) : "r"(a));
}
__device__ __forceinline__ void ldsm_x2_t(unsigned* r, unsigned a) {
    asm volatile("ldmatrix.sync.aligned.m8n8.x2.trans.shared.b16 {%0,%1}, [%2];"
        : "=r"(r[0]), "=r"(r[1]) : "r"(a));
}
// exp2 on packed half2 (one MUFU for two values)
__device__ __forceinline__ unsigned ex2_h2(unsigned x) {
    unsigned y;
    asm volatile("ex2.approx.f16x2 %0, %1;" : "=r"(y) : "r"(x));
    return y;
}

__device__ __forceinline__ void cp16(unsigned dst, const void* src) {
    asm volatile("cp.async.cg.shared.global [%0], [%1], 16;\n" :: "r"(dst), "l"(src));
}
__device__ __forceinline__ void cp_commit() {
    asm volatile("cp.async.commit_group;\n" ::);
}
template<int N>
__device__ __forceinline__ void cp_wait() {
    asm volatile("cp.async.wait_group %0;\n" :: "n"(N));
}

// ---------------------------------------------------------------------------
// Fused pre-pass (unchanged): weight transposes (+half), y->half, bias pack.
// ---------------------------------------------------------------------------
__device__ __forceinline__ void transp_tile(const float* __restrict__ in,
                                            __half* __restrict__ out,
                                            int K, int N, int nb, int kb,
                                            float (*t)[33], int tid)
{
    int tx = tid & 31, ty = tid >> 5;
#pragma unroll
    for (int i = 0; i < 32; i += 8)
        t[ty + i][tx] = in[(size_t)(kb + ty + i) * N + nb + tx];
    __syncthreads();
#pragma unroll
    for (int i = 0; i < 32; i += 8)
        out[(size_t)(nb + ty + i) * K + kb + tx] = __float2half(t[tx][ty + i]);
}

__global__ __launch_bounds__(256)
void prep(const float* __restrict__ y, __half* __restrict__ yh,
          const float* __restrict__ Wq, const float* __restrict__ Wk,
          const float* __restrict__ Wv, __half* __restrict__ wqkvT,
          const float* __restrict__ Wm, __half* __restrict__ wmT,
          const float* __restrict__ W1, __half* __restrict__ w1T,
          const float* __restrict__ W2, __half* __restrict__ w2T,
          const float* __restrict__ bq, const float* __restrict__ bk,
          const float* __restrict__ bv, float* __restrict__ bqkv)
{
    __shared__ float t[32][33];
    const int bid = blockIdx.x;
    const int tid = threadIdx.x;

    if (bid < 768) {
        int nbt = bid % 48, kbt = bid / 48;
        int nb = nbt << 5, kb = kbt << 5;
        const float* src = (nb < 512) ? Wq : (nb < 1024) ? Wk : Wv;
        int nloc = nb & 511;
        int tx = tid & 31, ty = tid >> 5;
#pragma unroll
        for (int i = 0; i < 32; i += 8)
            t[ty + i][tx] = src[(size_t)(kb + ty + i) * 512 + nloc + tx];
        __syncthreads();
#pragma unroll
        for (int i = 0; i < 32; i += 8)
            wqkvT[(size_t)(nb + ty + i) * 512 + kb + tx] = __float2half(t[tx][ty + i]);
    } else if (bid < 1792) {
        int r = bid - 768;
        transp_tile(Wm, wmT, 1024, 1024, (r % 32) << 5, (r / 32) << 5, t, tid);
    } else if (bid < 5888) {
        int r = bid - 1792;
        transp_tile(W1, w1T, 1024, 4096, (r % 128) << 5, (r / 128) << 5, t, tid);
    } else if (bid < 6912) {
        int r = bid - 5888;
        transp_tile(W2, w2T, 2048, 512, (r % 16) << 5, (r / 16) << 5, t, tid);
    } else if (bid < 7936) {
        size_t base = (size_t)(bid - 6912) * 8192 + (tid << 2);
#pragma unroll
        for (int j = 0; j < 8; j++) {
            size_t idx = base + (size_t)j * 1024;
            float4 v = *(const float4*)&y[idx];
            __half2 h0 = __floats2half2_rn(v.x, v.y);
            __half2 h1 = __floats2half2_rn(v.z, v.w);
            *(__half2*)&yh[idx]     = h0;
            *(__half2*)&yh[idx + 2] = h1;
        }
    } else {
#pragma unroll
        for (int j = 0; j < 6; j++) {
            int i = tid + (j << 8);
            int s = i >> 9, c = i & 511;
            const float* bs = (s == 0) ? bq : (s == 1) ? bk : bv;
            bqkv[i] = bs[c];
        }
    }
}

// ---------------------------------------------------------------------------
// fp16 tensor-core GEMM — EXACT R8/R13 config (measured at the legacy-HMMA
// hardware wall ~273 TF/s; do not touch): 128x128 tile, K-step 32, 256 thr,
// 8 warps 2Mx4N, warp tile 64x32, ldmatrix.x4, 3-stage cp.async,
// 60KB smem -> 2 CTAs/SM.
// ---------------------------------------------------------------------------
#define STAGES 3
#define ROW_BYTES 80
#define A_BYTES (128 * ROW_BYTES)
#define STAGE_BYTES (2 * A_BYTES)
#define GEMM_SMEM_BYTES (STAGES * STAGE_BYTES)  // 61440

#define GEMM_ISSUE(s_) do {                                                   \
    int ko_ = (s_) << 5;                                                      \
    unsigned sb_ = sbase + (unsigned)(((s_) % STAGES) * STAGE_BYTES);         \
    _Pragma("unroll")                                                         \
    for (int i_ = 0; i_ < 2; i_++) cp16(sb_ + a_sm[i_], a_gm[i_] + ko_);      \
    _Pragma("unroll")                                                         \
    for (int i_ = 0; i_ < 2; i_++)                                            \
        cp16(sb_ + A_BYTES + b_sm[i_], b_gm[i_] + ko_);                       \
} while (0)

template<bool GATHER_A, bool RELU, bool OUT_HALF>
__global__ __launch_bounds__(256, 2)
void hgemm(const __half* __restrict__ A, const __half* __restrict__ BT,
           const float* __restrict__ bias, void* __restrict__ Cv,
           int M, int N, int K)
{
    extern __shared__ unsigned char dsm[];
    const unsigned sbase = (unsigned)__cvta_generic_to_shared(dsm);

    const int tid  = threadIdx.x;
    const int row0 = blockIdx.y << 7;
    const int col0 = blockIdx.x << 7;
    const int lane = tid & 31;
    const int w    = tid >> 5;
    const int wm   = w & 1;
    const int wn   = w >> 1;
    const int tig  = lane & 3;
    const int grp  = lane >> 2;

    unsigned a_sm[2], b_sm[2];
    const __half* a_gm[2];
    const __half* b_gm[2];
#pragma unroll
    for (int i = 0; i < 2; i++) {
        int ci = tid + (i << 8);
        int r  = ci >> 2;
        int kc = (ci & 3) << 3;
        a_sm[i] = (unsigned)(r * ROW_BYTES + (kc << 1));
        b_sm[i] = a_sm[i];
        int grow = row0 + r;
        if (GATHER_A) {
            int bg = grow >> 9, l = grow & 511;
            int b  = bg & 15,  g = bg >> 4;
            a_gm[i] = A + (((size_t)b * 512 + l) * 1024 + (size_t)g * 512) + kc;
        } else {
            a_gm[i] = A + (size_t)grow * (size_t)K + kc;
        }
        b_gm[i] = BT + (size_t)(col0 + r) * (size_t)K + kc;
    }

    const unsigned a_ld = (unsigned)(((wm << 6) + (lane & 15)) * ROW_BYTES
                                     + (((lane >> 4) << 3) << 1));
    const unsigned b_ld = (unsigned)((((wn << 5) + (lane & 7)) * ROW_BYTES)
                                     + ((((lane >> 3) & 3) << 3) << 1));

    float acc[4][4][4];
#pragma unroll
    for (int mi = 0; mi < 4; mi++)
#pragma unroll
        for (int ni = 0; ni < 4; ni++)
#pragma unroll
            for (int j = 0; j < 4; j++) acc[mi][ni][j] = 0.f;

    GEMM_ISSUE(0); cp_commit();
    GEMM_ISSUE(1); cp_commit();

    const int nIter = K >> 5;
    for (int it = 0; it < nIter; ++it) {
        cp_wait<1>();
        __syncthreads();

        const unsigned stg = sbase + (unsigned)((it % STAGES) * STAGE_BYTES);

        unsigned bf[4][4];
#pragma unroll
        for (int ni = 0; ni < 4; ni++)
            ldsm_x4(bf[ni], stg + A_BYTES + b_ld + (unsigned)(ni * 8 * ROW_BYTES));

#pragma unroll
        for (int ks = 0; ks < 2; ks++) {
            unsigned af[4][4];
#pragma unroll
            for (int mi = 0; mi < 4; mi++)
                ldsm_x4(af[mi], stg + a_ld
                        + (unsigned)(mi * 16 * ROW_BYTES + (ks << 5)));
#pragma unroll
            for (int mi = 0; mi < 4; mi++)
#pragma unroll
                for (int ni = 0; ni < 4; ni++)
                    mma_f16(acc[mi][ni], af[mi], &bf[ni][ks << 1]);
        }

        int s = it + 2;
        if (s < nIter) GEMM_ISSUE(s);
        cp_commit();
    }

#pragma unroll
    for (int mi = 0; mi < 4; mi++) {
        int r = row0 + (wm << 6) + (mi << 4) + grp;
#pragma unroll
        for (int ni = 0; ni < 4; ni++) {
            int c = col0 + (wn << 5) + (ni << 3) + (tig << 1);
            float2 bv = *(const float2*)&bias[c];
            float v00 = acc[mi][ni][0] + bv.x;
            float v01 = acc[mi][ni][1] + bv.y;
            float v10 = acc[mi][ni][2] + bv.x;
            float v11 = acc[mi][ni][3] + bv.y;
            if (RELU) {
                v00 = fmaxf(v00, 0.f); v01 = fmaxf(v01, 0.f);
                v10 = fmaxf(v10, 0.f); v11 = fmaxf(v11, 0.f);
            }
            if (OUT_HALF) {
                __half* Ch = (__half*)Cv;
                *(__half2*)&Ch[(size_t)r * N + c]       = __floats2half2_rn(v00, v01);
                *(__half2*)&Ch[(size_t)(r + 8) * N + c] = __floats2half2_rn(v10, v11);
            } else {
                float* Cf = (float*)Cv;
                float2 o0; o0.x = v00; o0.y = v01;
                float2 o1; o1.x = v10; o1.y = v11;
                *(float2*)&Cf[(size_t)r * N + c]       = o0;
                *(float2*)&Cf[(size_t)(r + 8) * N + c] = o1;
            }
        }
    }
}

// ---------------------------------------------------------------------------
// Flash tensor-core attention (R13 structure), with:
//  * P = exp2 of packed half2 via ex2.approx.f16x2 (half the MUFU ops,
//    zero separate packing; log2e folded into scale/mask constants)
//  * row sums via ones-column MMA: V padding col 64 = 1.0, one extra
//    ldsm_x2.trans + m16n8k16 per kt accumulates sum into oS (rescaled
//    with o across chunks; exact fp32 accumulation)
// Grid = 1024 = (bg, head, q-half), 256 threads, 2 CTAs/SM.
// ---------------------------------------------------------------------------
#define ATTN_THREADS 256
#define QKV_STRIDE 1536
#define QP 72
#define ATTN_SMEM_BYTES ((128 + 256 + 256) * QP * 2)   // 92160
#define LOG2E 1.4426950408889634f

__global__ __launch_bounds__(ATTN_THREADS, 2)
void attn_mma(const __half* __restrict__ qkv, const void* __restrict__ maskp,
              __half* __restrict__ atted)
{
    extern __shared__ __half hs[];
    __half* Qs = hs;                 // 128 x QP
    __half* Ks = Qs + 128 * QP;      // 256 x QP
    __half* Vs = Ks + 256 * QP;      // 256 x QP
    __shared__ float mvals[256];

    const int bh   = blockIdx.x >> 1;
    const int qh   = blockIdx.x & 1;
    const int bg   = bh >> 4;
    const int h    = bh & 15;
    const int tid  = threadIdx.x;
    const int lane = tid & 31;
    const int w    = tid >> 5;
    const int lpar  = h >> 3;
    const int cbase = (h & 7) << 6;
    const int b = bg & 15;
    const int g = bg >> 4;
    const int h128 = qh << 7;

    unsigned word = ((const unsigned*)maskp)[tid];
    int is32 = __syncthreads_and(word <= 1u);

    const __half* base = qkv + (size_t)bg * 512 * QKV_STRIDE;

    for (int idx = tid; idx < 2048; idx += ATTN_THREADS) {
        int t  = idx >> 3;
        int d8 = (idx & 7) << 3;
        size_t off = (size_t)(2 * t + lpar) * QKV_STRIDE + cbase + d8;
        *(uint4*)&Ks[t * QP + d8] = *(const uint4*)(base + 512 + off);
        *(uint4*)&Vs[t * QP + d8] = *(const uint4*)(base + 1024 + off);
    }
    for (int idx = tid; idx < 1024; idx += ATTN_THREADS) {
        int t  = idx >> 3;
        int d8 = (idx & 7) << 3;
        size_t off = (size_t)(2 * (h128 + t) + lpar) * QKV_STRIDE + cbase + d8;
        *(uint4*)&Qs[t * QP + d8] = *(const uint4*)(base + off);
    }
    // ones column in V padding (col 64 = 1.0h, cols 65..71 = 0) -> row sums
    {
        uint4 ones = {0x00003C00u, 0u, 0u, 0u};
        *(uint4*)&Vs[tid * QP + 64] = ones;
    }
    {
        int mv = is32 ? ((const int*)maskp)[b * 256 + tid]
                      : (int)((const unsigned char*)maskp)[b * 256 + tid];
        mvals[tid] = mv ? (-1e9f * LOG2E) : 0.0f;   // log2-domain mask
    }
    __syncthreads();

    const unsigned qs0 = (unsigned)__cvta_generic_to_shared(Qs);
    const unsigned ks0 = (unsigned)__cvta_generic_to_shared(Ks);
    const unsigned vs0 = (unsigned)__cvta_generic_to_shared(Vs);

    const int lq = lane >> 2;
    const int lc = (lane & 3) << 1;
    const int qrow0 = w << 4;

    unsigned aq[4][4];
#pragma unroll
    for (int ks = 0; ks < 4; ks++) {
        unsigned addr = qs0 + (unsigned)(((qrow0 + (lane & 15)) * QP
                          + (ks << 4) + ((lane >> 4) << 3)) * 2);
        ldsm_x4(aq[ks], addr);
    }

    const float scale = 0.125f * LOG2E;   // log2-domain scores
    float m0 = -3.0e38f, m1 = -3.0e38f;   // running max (rows lq, lq+8)
    float o[8][4];
    float oS[4];                          // ones-column tile: row sums in col 0
#pragma unroll
    for (int dn = 0; dn < 8; dn++) {
        o[dn][0] = 0.f; o[dn][1] = 0.f; o[dn][2] = 0.f; o[dn][3] = 0.f;
    }
    oS[0] = 0.f; oS[1] = 0.f; oS[2] = 0.f; oS[3] = 0.f;

#pragma unroll 1
    for (int c = 0; c < 2; c++) {
        const int kbase = c << 7;

        // --- S chunk (log2 domain): 16 n-tiles x 4 f32 ---
        float acc[16][4];
#pragma unroll
        for (int nt = 0; nt < 16; nt++) {
            acc[nt][0] = 0.f; acc[nt][1] = 0.f; acc[nt][2] = 0.f; acc[nt][3] = 0.f;
            unsigned bk[2][4];
#pragma unroll
            for (int j = 0; j < 2; j++) {
                unsigned addr = ks0 + (unsigned)(((kbase + (nt << 3) + (lane & 7)) * QP
                                  + (j << 5) + ((lane >> 3) << 3)) * 2);
                ldsm_x4(bk[j], addr);
            }
            mma_f16(acc[nt], aq[0], &bk[0][0]);
            mma_f16(acc[nt], aq[1], &bk[0][2]);
            mma_f16(acc[nt], aq[2], &bk[1][0]);
            mma_f16(acc[nt], aq[3], &bk[1][2]);
        }

        // --- scale + mask + chunk max ---
        float cm0 = -3.0e38f, cm1 = -3.0e38f;
#pragma unroll
        for (int nt = 0; nt < 16; nt++) {
            float mv0 = mvals[kbase + (nt << 3) + lc];
            float mv1 = mvals[kbase + (nt << 3) + lc + 1];
            acc[nt][0] = acc[nt][0] * scale + mv0;
            acc[nt][1] = acc[nt][1] * scale + mv1;
            acc[nt][2] = acc[nt][2] * scale + mv0;
            acc[nt][3] = acc[nt][3] * scale + mv1;
            cm0 = fmaxf(cm0, fmaxf(acc[nt][0], acc[nt][1]));
            cm1 = fmaxf(cm1, fmaxf(acc[nt][2], acc[nt][3]));
        }
        cm0 = fmaxf(cm0, __shfl_xor_sync(0xffffffffu, cm0, 1));
        cm0 = fmaxf(cm0, __shfl_xor_sync(0xffffffffu, cm0, 2));
        cm1 = fmaxf(cm1, __shfl_xor_sync(0xffffffffu, cm1, 1));
        cm1 = fmaxf(cm1, __shfl_xor_sync(0xffffffffu, cm1, 2));

        // --- running rescale (exp2 domain) ---
        float nm0 = fmaxf(m0, cm0);
        float nm1 = fmaxf(m1, cm1);
        float f0 = exp2f(m0 - nm0);       // 0 on first chunk
        float f1 = exp2f(m1 - nm1);
        m0 = nm0; m1 = nm1;
#pragma unroll
        for (int dn = 0; dn < 8; dn++) {
            o[dn][0] *= f0; o[dn][1] *= f0;
            o[dn][2] *= f1; o[dn][3] *= f1;
        }
        oS[0] *= f0; oS[1] *= f0; oS[2] *= f1; oS[3] *= f1;

        // --- P = exp2(s - m) directly in packed half2 ---
        unsigned P[16][2];                // [nt][0]=rows lq pair, [1]=rows lq+8 pair
#pragma unroll
        for (int nt = 0; nt < 16; nt++) {
            __half2 x01 = __floats2half2_rn(acc[nt][0] - m0, acc[nt][1] - m0);
            __half2 x23 = __floats2half2_rn(acc[nt][2] - m1, acc[nt][3] - m1);
            P[nt][0] = ex2_h2(*(unsigned*)&x01);
            P[nt][1] = ex2_h2(*(unsigned*)&x23);
        }

        // --- O += P V ; row sums via ones column (col 64) ---
#pragma unroll
        for (int kt = 0; kt < 8; kt++) {
            unsigned pa[4];
            pa[0] = P[2*kt][0];   pa[1] = P[2*kt][1];
            pa[2] = P[2*kt+1][0]; pa[3] = P[2*kt+1][1];
#pragma unroll
            for (int p = 0; p < 4; p++) {
                unsigned bv[4];
                unsigned addr = vs0 + (unsigned)(((kbase + (kt << 4)
                                  + ((lane >> 3) & 1) * 8 + (lane & 7)) * QP
                                  + (p << 4) + ((lane >> 4) << 3)) * 2);
                ldsm_x4_t(bv, addr);
                mma_f16(o[2*p],     pa, &bv[0]);
                mma_f16(o[2*p + 1], pa, &bv[2]);
            }
            // ones-column tile (V cols 64..71)
            {
                unsigned bs[2];
                unsigned addr = vs0 + (unsigned)(((kbase + (kt << 4)
                                  + (lane & 15)) * QP + 64) * 2);
                ldsm_x2_t(bs, addr);
                mma_f16(oS, pa, bs);
            }
        }
    }

    // row sums live in col 0 of the ones tile (lanes with tig==0)
    float s0 = __shfl_sync(0xffffffffu, oS[0], lane & 28);
    float s1 = __shfl_sync(0xffffffffu, oS[2], lane & 28);
    const float inv0 = 1.f / s0;
    const float inv1 = 1.f / s1;

    const int t0 = h128 + qrow0 + lq;
#pragma unroll
    for (int dn = 0; dn < 8; dn++) {
        int d = (dn << 3) + lc;
        __half2 h0 = __floats2half2_rn(o[dn][0] * inv0, o[dn][1] * inv0);
        __half2 h1 = __floats2half2_rn(o[dn][2] * inv1, o[dn][3] * inv1);
        size_t ob0 = ((size_t)b * 512 + (2 * t0 + lpar)) * 1024
                   + (size_t)g * 512 + cbase + d;
        size_t ob1 = ((size_t)b * 512 + (2 * (t0 + 8) + lpar)) * 1024
                   + (size_t)g * 512 + cbase + d;
        *(__half2*)&atted[ob0] = h0;
        *(__half2*)&atted[ob1] = h1;
    }
}

// ---------------------------------------------------------------------------
// Residual-add + LayerNorm over rows of 1024. One block (256 thr) per row.
// ---------------------------------------------------------------------------
__global__ __launch_bounds__(256)
void add_ln_kernel(const float* __restrict__ res, const float* __restrict__ dlt,
                   const float* __restrict__ gamma, const float* __restrict__ beta,
                   float* __restrict__ out, __half* __restrict__ outh)
{
    __shared__ float red[8];
    __shared__ float s_mean, s_inv;
    const int row = blockIdx.x;
    const int tid = threadIdx.x;
    const size_t base = (size_t)row * 1024;
    const int c0 = tid << 2;

    float4 xr = *(const float4*)&res[base + c0];
    float4 xd = *(const float4*)&dlt[base + c0];
    float x[4] = { xr.x + xd.x, xr.y + xd.y, xr.z + xd.z, xr.w + xd.w };
    float s = x[0] + x[1] + x[2] + x[3];
#pragma unroll
    for (int o = 16; o; o >>= 1) s += __shfl_xor_sync(0xffffffffu, s, o);
    if ((tid & 31) == 0) red[tid >> 5] = s;
    __syncthreads();
    if (tid < 32) {
        float t = (tid < 8) ? red[tid] : 0.f;
#pragma unroll
        for (int o = 4; o; o >>= 1) t += __shfl_xor_sync(0xffffffffu, t, o);
        if (tid == 0) s_mean = t * (1.f / 1024.f);
    }
    __syncthreads();
    const float mean = s_mean;

    float vs = 0.f;
#pragma unroll
    for (int i = 0; i < 4; i++) { float d = x[i] - mean; vs += d * d; }
#pragma unroll
    for (int o = 16; o; o >>= 1) vs += __shfl_xor_sync(0xffffffffu, vs, o);
    if ((tid & 31) == 0) red[tid >> 5] = vs;
    __syncthreads();
    if (tid < 32) {
        float t = (tid < 8) ? red[tid] : 0.f;
#pragma unroll
        for (int o = 4; o; o >>= 1) t += __shfl_xor_sync(0xffffffffu, t, o);
        if (tid == 0) s_inv = rsqrtf(t * (1.f / 1024.f) + 1e-6f);
    }
    __syncthreads();
    const float inv = s_inv;

    float4 gm = *(const float4*)&gamma[c0];
    float4 bt = *(const float4*)&beta[c0];
    float4 o4;
    o4.x = (x[0] - mean) * inv * gm.x + bt.x;
    o4.y = (x[1] - mean) * inv * gm.y + bt.y;
    o4.z = (x[2] - mean) * inv * gm.z + bt.z;
    o4.w = (x[3] - mean) * inv * gm.w + bt.w;
    *(float4*)&out[base + c0] = o4;
    if (outh) {
        __half2 h0 = __floats2half2_rn(o4.x, o4.y);
        __half2 h1 = __floats2half2_rn(o4.z, o4.w);
        *(__half2*)&outh[base + c0]     = h0;
        *(__half2*)&outh[base + c0 + 2] = h1;
    }
}

// ---------------------------------------------------------------------------
// Launch.  8 kernels total.
// ---------------------------------------------------------------------------
extern "C" void kernel_launch(void* const* d_in, const int* in_sizes, int n_in,
                              void* d_out, int out_size)
{
    const float* y   = (const float*)d_in[0];
    const void*  msk = d_in[1];
    const float* Wv  = (const float*)d_in[2];
    const float* bv  = (const float*)d_in[3];
    const float* Wk  = (const float*)d_in[4];
    const float* bk  = (const float*)d_in[5];
    const float* Wq  = (const float*)d_in[6];
    const float* bq  = (const float*)d_in[7];
    const float* Wm  = (const float*)d_in[8];
    const float* bm  = (const float*)d_in[9];
    const float* W1  = (const float*)d_in[10];
    const float* b1  = (const float*)d_in[11];
    const float* W2  = (const float*)d_in[12];
    const float* b2  = (const float*)d_in[13];
    const float* g1  = (const float*)d_in[14];
    const float* be1 = (const float*)d_in[15];
    const float* g2  = (const float*)d_in[16];
    const float* be2 = (const float*)d_in[17];
    float* out = (float*)d_out;

    __half *yh, *wqkvT, *wmT, *w1T, *w2T, *qkv, *att, *y1h, *h1;
    float *bqkv, *mh, *y1, *ff;
    cudaGetSymbolAddress((void**)&yh,    g_yh);
    cudaGetSymbolAddress((void**)&wqkvT, g_wqkvT);
    cudaGetSymbolAddress((void**)&bqkv,  g_bqkv);
    cudaGetSymbolAddress((void**)&wmT,   g_wmT);
    cudaGetSymbolAddress((void**)&w1T,   g_w1T);
    cudaGetSymbolAddress((void**)&w2T,   g_w2T);
    cudaGetSymbolAddress((void**)&qkv,   g_qkv);
    cudaGetSymbolAddress((void**)&att,   g_att);
    cudaGetSymbolAddress((void**)&mh,    g_mh);
    cudaGetSymbolAddress((void**)&y1,    g_y1);
    cudaGetSymbolAddress((void**)&y1h,   g_y1h);
    cudaGetSymbolAddress((void**)&h1,    g_h1);
    cudaGetSymbolAddress((void**)&ff,    g_ff);

    cudaFuncSetAttribute(attn_mma,
                         cudaFuncAttributeMaxDynamicSharedMemorySize, ATTN_SMEM_BYTES);
    cudaFuncSetAttribute(hgemm<true,  false, true >,
                         cudaFuncAttributeMaxDynamicSharedMemorySize, GEMM_SMEM_BYTES);
    cudaFuncSetAttribute(hgemm<false, false, false>,
                         cudaFuncAttributeMaxDynamicSharedMemorySize, GEMM_SMEM_BYTES);
    cudaFuncSetAttribute(hgemm<false, true,  true >,
                         cudaFuncAttributeMaxDynamicSharedMemorySize, GEMM_SMEM_BYTES);

    dim3 blk(256);

    // 1) fused pre-pass
    prep<<<7937, blk>>>(y, yh, Wq, Wk, Wv, wqkvT, Wm, wmT, W1, w1T, W2, w2T,
                        bq, bk, bv, bqkv);

    // 2) Fused QKV: (16384,1536) = gather(yh) @ Wqkv + bqkv -> half
    hgemm<true,  false, true ><<<dim3(12, 128), blk, GEMM_SMEM_BYTES>>>(yh, wqkvT, bqkv, qkv, 16384, 1536, 512);

    // 3) Flash tensor-core attention -> att (half, B,L,H layout)
    attn_mma<<<1024, ATTN_THREADS, ATTN_SMEM_BYTES>>>(qkv, msk, att);

    // 4) Merge: (8192,1024) @ Wm + bm -> fp32
    hgemm<false, false, false><<<dim3(8, 64), blk, GEMM_SMEM_BYTES>>>(att, wmT, bm, mh, 8192, 1024, 1024);

    // 5) y1 = LN(y + merge): fp32 (residual) + half (FFN1 input)
    add_ln_kernel<<<8192, blk>>>(y, mh, g1, be1, y1, y1h);

    // 6) FFN1: (8192,1024) @ W1 + b1, relu -> half
    hgemm<false, true,  true ><<<dim3(32, 64), blk, GEMM_SMEM_BYTES>>>(y1h, w1T, b1, h1, 8192, 4096, 1024);

    // 7) FFN2: (16384,2048) @ W2 + b2 -> fp32
    hgemm<false, false, false><<<dim3(4, 128), blk, GEMM_SMEM_BYTES>>>(h1, w2T, b2, ff, 16384, 512, 2048);

    // 8) out = LN(y1 + ff), full fp32
    add_ln_kernel<<<8192, blk>>>(y1, ff, g2, be2, out, (__half*)0);
}

// round 15
// speedup vs baseline: 1.2335x; 1.1435x over previous
#include <cuda_runtime.h>
#include <cuda_fp16.h>
#include <math.h>
#include <stdint.h>

// ---------------------------------------------------------------------------
// Problem constants: B=16, L=512, H=1024, G=2, NH=16, DH=64, FF=4096,
//                    DM=512, LG=256
// ---------------------------------------------------------------------------

// Scratch (device globals; allocation inside kernel_launch is forbidden)
__device__ __half g_yh   [16u*512u*1024u];
__device__ __half g_wqkvT[1536u*512u];
__device__ float  g_bqkv [1536u];
__device__ __half g_wmT  [1024u*1024u];
__device__ __half g_w1T  [4096u*1024u];
__device__ __half g_w2T  [512u*2048u];
__device__ __half g_qkv  [16384u*1536u];
__device__ __half g_att  [16u*512u*1024u];
__device__ __half g_mh   [16u*512u*1024u];   // merge out (half)
__device__ float  g_y1   [16u*512u*1024u];
__device__ __half g_y1h  [16u*512u*1024u];
__device__ __half g_h1   [8192u*4096u];
__device__ __half g_ff   [16u*512u*1024u];   // FFN2 out (half)

// ---------------------------------------------------------------------------
// Helpers
// ---------------------------------------------------------------------------
__device__ __forceinline__ void mma_f16(float* d, const unsigned* a, const unsigned* b) {
    asm volatile(
        "mma.sync.aligned.m16n8k16.row.col.f32.f16.f16.f32 "
        "{%0,%1,%2,%3}, {%4,%5,%6,%7}, {%8,%9}, {%0,%1,%2,%3};\n"
        : "+f"(d[0]), "+f"(d[1]), "+f"(d[2]), "+f"(d[3])
        : "r"(a[0]), "r"(a[1]), "r"(a[2]), "r"(a[3]), "r"(b[0]), "r"(b[1]));
}

__device__ __forceinline__ void ldsm_x4(unsigned* r, unsigned a) {
    asm volatile("ldmatrix.sync.aligned.m8n8.x4.shared.b16 {%0,%1,%2,%3}, [%4];"
        : "=r"(r[0]), "=r"(r[1]), "=r"(r[2]), "=r"(r[3]) : "r"(a));
}
__device__ __forceinline__ void ldsm_x4_t(unsigned* r, unsigned a) {
    asm volatile("ldmatrix.sync.aligned.m8n8.x4.trans.shared.b16 {%0,%1,%2,%3}, [%4];"
        : "=r"(r[0]), "=r"(r[1]), "=r"(r[2]), "=r"(r[3]) : "r"(a));
}
__device__ __forceinline__ void ldsm_x2_t(unsigned* r, unsigned a) {
    asm volatile("ldmatrix.sync.aligned.m8n8.x2.trans.shared.b16 {%0,%1}, [%2];"
        : "=r"(r[0]), "=r"(r[1]) : "r"(a));
}
__device__ __forceinline__ unsigned ex2_h2(unsigned x) {
    unsigned y;
    asm volatile("ex2.approx.f16x2 %0, %1;" : "=r"(y) : "r"(x));
    return y;
}

__device__ __forceinline__ void cp16(unsigned dst, const void* src) {
    asm volatile("cp.async.cg.shared.global [%0], [%1], 16;\n" :: "r"(dst), "l"(src));
}
__device__ __forceinline__ void cp_commit() {
    asm volatile("cp.async.commit_group;\n" ::);
}
template<int N>
__device__ __forceinline__ void cp_wait() {
    asm volatile("cp.async.wait_group %0;\n" :: "n"(N));
}

// ---------------------------------------------------------------------------
// Fused pre-pass (unchanged): weight transposes (+half), y->half, bias pack.
// ---------------------------------------------------------------------------
__device__ __forceinline__ void transp_tile(const float* __restrict__ in,
                                            __half* __restrict__ out,
                                            int K, int N, int nb, int kb,
                                            float (*t)[33], int tid)
{
    int tx = tid & 31, ty = tid >> 5;
#pragma unroll
    for (int i = 0; i < 32; i += 8)
        t[ty + i][tx] = in[(size_t)(kb + ty + i) * N + nb + tx];
    __syncthreads();
#pragma unroll
    for (int i = 0; i < 32; i += 8)
        out[(size_t)(nb + ty + i) * K + kb + tx] = __float2half(t[tx][ty + i]);
}

__global__ __launch_bounds__(256)
void prep(const float* __restrict__ y, __half* __restrict__ yh,
          const float* __restrict__ Wq, const float* __restrict__ Wk,
          const float* __restrict__ Wv, __half* __restrict__ wqkvT,
          const float* __restrict__ Wm, __half* __restrict__ wmT,
          const float* __restrict__ W1, __half* __restrict__ w1T,
          const float* __restrict__ W2, __half* __restrict__ w2T,
          const float* __restrict__ bq, const float* __restrict__ bk,
          const float* __restrict__ bv, float* __restrict__ bqkv)
{
    __shared__ float t[32][33];
    const int bid = blockIdx.x;
    const int tid = threadIdx.x;

    if (bid < 768) {
        int nbt = bid % 48, kbt = bid / 48;
        int nb = nbt << 5, kb = kbt << 5;
        const float* src = (nb < 512) ? Wq : (nb < 1024) ? Wk : Wv;
        int nloc = nb & 511;
        int tx = tid & 31, ty = tid >> 5;
#pragma unroll
        for (int i = 0; i < 32; i += 8)
            t[ty + i][tx] = src[(size_t)(kb + ty + i) * 512 + nloc + tx];
        __syncthreads();
#pragma unroll
        for (int i = 0; i < 32; i += 8)
            wqkvT[(size_t)(nb + ty + i) * 512 + kb + tx] = __float2half(t[tx][ty + i]);
    } else if (bid < 1792) {
        int r = bid - 768;
        transp_tile(Wm, wmT, 1024, 1024, (r % 32) << 5, (r / 32) << 5, t, tid);
    } else if (bid < 5888) {
        int r = bid - 1792;
        transp_tile(W1, w1T, 1024, 4096, (r % 128) << 5, (r / 128) << 5, t, tid);
    } else if (bid < 6912) {
        int r = bid - 5888;
        transp_tile(W2, w2T, 2048, 512, (r % 16) << 5, (r / 16) << 5, t, tid);
    } else if (bid < 7936) {
        size_t base = (size_t)(bid - 6912) * 8192 + (tid << 2);
#pragma unroll
        for (int j = 0; j < 8; j++) {
            size_t idx = base + (size_t)j * 1024;
            float4 v = *(const float4*)&y[idx];
            __half2 h0 = __floats2half2_rn(v.x, v.y);
            __half2 h1 = __floats2half2_rn(v.z, v.w);
            *(__half2*)&yh[idx]     = h0;
            *(__half2*)&yh[idx + 2] = h1;
        }
    } else {
#pragma unroll
        for (int j = 0; j < 6; j++) {
            int i = tid + (j << 8);
            int s = i >> 9, c = i & 511;
            const float* bs = (s == 0) ? bq : (s == 1) ? bk : bv;
            bqkv[i] = bs[c];
        }
    }
}

// ---------------------------------------------------------------------------
// fp16 tensor-core GEMM (mma.sync m16n8k16, fp32 accumulate).
// Block tile 128x128, K-step 64 (HALF the barriers/waits of the K-32 loop),
// XOR-swizzled 128B rows (chunk ^= row&7; conflict-free for cp.async stores
// and all ldmatrix patterns since row&7 == lane&7 everywhere).
// 256 thr, 8 warps 2Mx4N, warp tile 64x32.  3-stage cp.async,
// 96KB smem/CTA -> 2 CTAs/SM (192KB).  BT = pre-transposed (N,K).
// Requires M%128==0, N%128==0, K%64==0.
// ---------------------------------------------------------------------------
#define STAGES 3
#define TILE_BYTES 16384                // 128 rows x 128B (64 halves, no pad)
#define STAGE_BYTES (2 * TILE_BYTES)    // 32768
#define GEMM_SMEM_BYTES (STAGES * STAGE_BYTES)  // 98304

#define GEMM_ISSUE(s_) do {                                                   \
    int ko_ = (s_) << 6;                                                      \
    unsigned sb_ = sbase + (unsigned)(((s_) % STAGES) * STAGE_BYTES);         \
    _Pragma("unroll")                                                         \
    for (int i_ = 0; i_ < 4; i_++)                                            \
        cp16(sb_ + a_sm0 + (unsigned)(i_ << 12),                              \
             a_gm0 + (size_t)i_ * a_str + ko_);                               \
    _Pragma("unroll")                                                         \
    for (int i_ = 0; i_ < 4; i_++)                                            \
        cp16(sb_ + TILE_BYTES + a_sm0 + (unsigned)(i_ << 12),                 \
             b_gm0 + (size_t)(i_ << 5) * (size_t)K + ko_);                    \
} while (0)

template<bool GATHER_A, bool RELU, bool OUT_HALF>
__global__ __launch_bounds__(256, 2)
void hgemm(const __half* __restrict__ A, const __half* __restrict__ BT,
           const float* __restrict__ bias, void* __restrict__ Cv,
           int M, int N, int K)
{
    extern __shared__ unsigned char dsm[];
    const unsigned sbase = (unsigned)__cvta_generic_to_shared(dsm);

    const int tid  = threadIdx.x;
    const int row0 = blockIdx.y << 7;
    const int col0 = blockIdx.x << 7;
    const int lane = tid & 31;
    const int w    = tid >> 5;
    const int wm   = w & 1;
    const int wn   = w >> 1;
    const int tig  = lane & 3;
    const int grp  = lane >> 2;
    const int lo7  = lane & 7;

    // copy descriptors (rows stride 32 between the 4 chunks; row&7 invariant)
    const int cr = tid >> 3;             // row 0..31
    const int lc = tid & 7;              // logical 16B chunk
    const unsigned a_sm0 = (unsigned)((cr << 7) + ((lc ^ (cr & 7)) << 4));
    const int kc0 = lc << 3;             // k offset in halves
    const __half* a_gm0;
    size_t a_str;
    if (GATHER_A) {
        int grow = row0 + cr;
        int bg = grow >> 9, l = grow & 511;
        int b  = bg & 15,  g = bg >> 4;
        a_gm0 = A + (((size_t)b * 512 + l) * 1024 + (size_t)g * 512) + kc0;
        a_str = (size_t)32 * 1024;
    } else {
        a_gm0 = A + (size_t)(row0 + cr) * (size_t)K + kc0;
        a_str = (size_t)32 * (size_t)K;
    }
    const __half* b_gm0 = BT + (size_t)(col0 + cr) * (size_t)K + kc0;

    // ldmatrix bases + swizzled chunk tables
    const unsigned a_base = (unsigned)(((wm << 6) + (lane & 15)) << 7);
    unsigned a_ck[4];
#pragma unroll
    for (int ks = 0; ks < 4; ks++)
        a_ck[ks] = (unsigned)((((ks << 1) + (lane >> 4)) ^ lo7) << 4);
    const unsigned b_base = (unsigned)(((wn << 5) + lo7) << 7);
    unsigned b_ck[2];
#pragma unroll
    for (int j = 0; j < 2; j++)
        b_ck[j] = (unsigned)((((j << 2) + ((lane >> 3) & 3)) ^ lo7) << 4);

    float acc[4][4][4];
#pragma unroll
    for (int mi = 0; mi < 4; mi++)
#pragma unroll
        for (int ni = 0; ni < 4; ni++)
#pragma unroll
            for (int j = 0; j < 4; j++) acc[mi][ni][j] = 0.f;

    GEMM_ISSUE(0); cp_commit();
    GEMM_ISSUE(1); cp_commit();

    const int nIter = K >> 6;
    for (int it = 0; it < nIter; ++it) {
        cp_wait<1>();
        __syncthreads();

        const unsigned stg  = sbase + (unsigned)((it % STAGES) * STAGE_BYTES);
        const unsigned stgB = stg + TILE_BYTES;

        unsigned bf[4][4];   // current k32 half of B for all 4 n-tiles
#pragma unroll
        for (int ks = 0; ks < 4; ks++) {
            if ((ks & 1) == 0) {
#pragma unroll
                for (int ni = 0; ni < 4; ni++)
                    ldsm_x4(bf[ni], stgB + b_base + (unsigned)(ni << 10)
                                  + b_ck[ks >> 1]);
            }
            unsigned af[4][4];
#pragma unroll
            for (int mi = 0; mi < 4; mi++)
                ldsm_x4(af[mi], stg + a_base + (unsigned)(mi << 11) + a_ck[ks]);
#pragma unroll
            for (int mi = 0; mi < 4; mi++)
#pragma unroll
                for (int ni = 0; ni < 4; ni++)
                    mma_f16(acc[mi][ni], af[mi], &bf[ni][(ks & 1) << 1]);
        }

        int s = it + 2;
        if (s < nIter) GEMM_ISSUE(s);
        cp_commit();
    }

#pragma unroll
    for (int mi = 0; mi < 4; mi++) {
        int r = row0 + (wm << 6) + (mi << 4) + grp;
#pragma unroll
        for (int ni = 0; ni < 4; ni++) {
            int c = col0 + (wn << 5) + (ni << 3) + (tig << 1);
            float2 bv = *(const float2*)&bias[c];
            float v00 = acc[mi][ni][0] + bv.x;
            float v01 = acc[mi][ni][1] + bv.y;
            float v10 = acc[mi][ni][2] + bv.x;
            float v11 = acc[mi][ni][3] + bv.y;
            if (RELU) {
                v00 = fmaxf(v00, 0.f); v01 = fmaxf(v01, 0.f);
                v10 = fmaxf(v10, 0.f); v11 = fmaxf(v11, 0.f);
            }
            if (OUT_HALF) {
                __half* Ch = (__half*)Cv;
                *(__half2*)&Ch[(size_t)r * N + c]       = __floats2half2_rn(v00, v01);
                *(__half2*)&Ch[(size_t)(r + 8) * N + c] = __floats2half2_rn(v10, v11);
            } else {
                float* Cf = (float*)Cv;
                float2 o0; o0.x = v00; o0.y = v01;
                float2 o1; o1.x = v10; o1.y = v11;
                *(float2*)&Cf[(size_t)r * N + c]       = o0;
                *(float2*)&Cf[(size_t)(r + 8) * N + c] = o1;
            }
        }
    }
}

// ---------------------------------------------------------------------------
// Flash tensor-core attention (R14, unchanged: exp2-h2 softmax, ones-column
// row sums, 2-chunk flash, 2 CTAs/SM).
// ---------------------------------------------------------------------------
#define ATTN_THREADS 256
#define QKV_STRIDE 1536
#define QP 72
#define ATTN_SMEM_BYTES ((128 + 256 + 256) * QP * 2)   // 92160
#define LOG2E 1.4426950408889634f

__global__ __launch_bounds__(ATTN_THREADS, 2)
void attn_mma(const __half* __restrict__ qkv, const void* __restrict__ maskp,
              __half* __restrict__ atted)
{
    extern __shared__ __half hs[];
    __half* Qs = hs;
    __half* Ks = Qs + 128 * QP;
    __half* Vs = Ks + 256 * QP;
    __shared__ float mvals[256];

    const int bh   = blockIdx.x >> 1;
    const int qh   = blockIdx.x & 1;
    const int bg   = bh >> 4;
    const int h    = bh & 15;
    const int tid  = threadIdx.x;
    const int lane = tid & 31;
    const int w    = tid >> 5;
    const int lpar  = h >> 3;
    const int cbase = (h & 7) << 6;
    const int b = bg & 15;
    const int g = bg >> 4;
    const int h128 = qh << 7;

    unsigned word = ((const unsigned*)maskp)[tid];
    int is32 = __syncthreads_and(word <= 1u);

    const __half* base = qkv + (size_t)bg * 512 * QKV_STRIDE;

    for (int idx = tid; idx < 2048; idx += ATTN_THREADS) {
        int t  = idx >> 3;
        int d8 = (idx & 7) << 3;
        size_t off = (size_t)(2 * t + lpar) * QKV_STRIDE + cbase + d8;
        *(uint4*)&Ks[t * QP + d8] = *(const uint4*)(base + 512 + off);
        *(uint4*)&Vs[t * QP + d8] = *(const uint4*)(base + 1024 + off);
    }
    for (int idx = tid; idx < 1024; idx += ATTN_THREADS) {
        int t  = idx >> 3;
        int d8 = (idx & 7) << 3;
        size_t off = (size_t)(2 * (h128 + t) + lpar) * QKV_STRIDE + cbase + d8;
        *(uint4*)&Qs[t * QP + d8] = *(const uint4*)(base + off);
    }
    {
        uint4 ones = {0x00003C00u, 0u, 0u, 0u};
        *(uint4*)&Vs[tid * QP + 64] = ones;
    }
    {
        int mv = is32 ? ((const int*)maskp)[b * 256 + tid]
                      : (int)((const unsigned char*)maskp)[b * 256 + tid];
        mvals[tid] = mv ? (-1e9f * LOG2E) : 0.0f;
    }
    __syncthreads();

    const unsigned qs0 = (unsigned)__cvta_generic_to_shared(Qs);
    const unsigned ks0 = (unsigned)__cvta_generic_to_shared(Ks);
    const unsigned vs0 = (unsigned)__cvta_generic_to_shared(Vs);

    const int lq = lane >> 2;
    const int lc = (lane & 3) << 1;
    const int qrow0 = w << 4;

    unsigned aq[4][4];
#pragma unroll
    for (int ks = 0; ks < 4; ks++) {
        unsigned addr = qs0 + (unsigned)(((qrow0 + (lane & 15)) * QP
                          + (ks << 4) + ((lane >> 4) << 3)) * 2);
        ldsm_x4(aq[ks], addr);
    }

    const float scale = 0.125f * LOG2E;
    float m0 = -3.0e38f, m1 = -3.0e38f;
    float o[8][4];
    float oS[4];
#pragma unroll
    for (int dn = 0; dn < 8; dn++) {
        o[dn][0] = 0.f; o[dn][1] = 0.f; o[dn][2] = 0.f; o[dn][3] = 0.f;
    }
    oS[0] = 0.f; oS[1] = 0.f; oS[2] = 0.f; oS[3] = 0.f;

#pragma unroll 1
    for (int c = 0; c < 2; c++) {
        const int kbase = c << 7;

        float acc[16][4];
#pragma unroll
        for (int nt = 0; nt < 16; nt++) {
            acc[nt][0] = 0.f; acc[nt][1] = 0.f; acc[nt][2] = 0.f; acc[nt][3] = 0.f;
            unsigned bk[2][4];
#pragma unroll
            for (int j = 0; j < 2; j++) {
                unsigned addr = ks0 + (unsigned)(((kbase + (nt << 3) + (lane & 7)) * QP
                                  + (j << 5) + ((lane >> 3) << 3)) * 2);
                ldsm_x4(bk[j], addr);
            }
            mma_f16(acc[nt], aq[0], &bk[0][0]);
            mma_f16(acc[nt], aq[1], &bk[0][2]);
            mma_f16(acc[nt], aq[2], &bk[1][0]);
            mma_f16(acc[nt], aq[3], &bk[1][2]);
        }

        float cm0 = -3.0e38f, cm1 = -3.0e38f;
#pragma unroll
        for (int nt = 0; nt < 16; nt++) {
            float mv0 = mvals[kbase + (nt << 3) + lc];
            float mv1 = mvals[kbase + (nt << 3) + lc + 1];
            acc[nt][0] = acc[nt][0] * scale + mv0;
            acc[nt][1] = acc[nt][1] * scale + mv1;
            acc[nt][2] = acc[nt][2] * scale + mv0;
            acc[nt][3] = acc[nt][3] * scale + mv1;
            cm0 = fmaxf(cm0, fmaxf(acc[nt][0], acc[nt][1]));
            cm1 = fmaxf(cm1, fmaxf(acc[nt][2], acc[nt][3]));
        }
        cm0 = fmaxf(cm0, __shfl_xor_sync(0xffffffffu, cm0, 1));
        cm0 = fmaxf(cm0, __shfl_xor_sync(0xffffffffu, cm0, 2));
        cm1 = fmaxf(cm1, __shfl_xor_sync(0xffffffffu, cm1, 1));
        cm1 = fmaxf(cm1, __shfl_xor_sync(0xffffffffu, cm1, 2));

        float nm0 = fmaxf(m0, cm0);
        float nm1 = fmaxf(m1, cm1);
        float f0 = exp2f(m0 - nm0);
        float f1 = exp2f(m1 - nm1);
        m0 = nm0; m1 = nm1;
#pragma unroll
        for (int dn = 0; dn < 8; dn++) {
            o[dn][0] *= f0; o[dn][1] *= f0;
            o[dn][2] *= f1; o[dn][3] *= f1;
        }
        oS[0] *= f0; oS[1] *= f0; oS[2] *= f1; oS[3] *= f1;

        unsigned P[16][2];
#pragma unroll
        for (int nt = 0; nt < 16; nt++) {
            __half2 x01 = __floats2half2_rn(acc[nt][0] - m0, acc[nt][1] - m0);
            __half2 x23 = __floats2half2_rn(acc[nt][2] - m1, acc[nt][3] - m1);
            P[nt][0] = ex2_h2(*(unsigned*)&x01);
            P[nt][1] = ex2_h2(*(unsigned*)&x23);
        }

#pragma unroll
        for (int kt = 0; kt < 8; kt++) {
            unsigned pa[4];
            pa[0] = P[2*kt][0];   pa[1] = P[2*kt][1];
            pa[2] = P[2*kt+1][0]; pa[3] = P[2*kt+1][1];
#pragma unroll
            for (int p = 0; p < 4; p++) {
                unsigned bv[4];
                unsigned addr = vs0 + (unsigned)(((kbase + (kt << 4)
                                  + ((lane >> 3) & 1) * 8 + (lane & 7)) * QP
                                  + (p << 4) + ((lane >> 4) << 3)) * 2);
                ldsm_x4_t(bv, addr);
                mma_f16(o[2*p],     pa, &bv[0]);
                mma_f16(o[2*p + 1], pa, &bv[2]);
            }
            {
                unsigned bs[2];
                unsigned addr = vs0 + (unsigned)(((kbase + (kt << 4)
                                  + (lane & 15)) * QP + 64) * 2);
                ldsm_x2_t(bs, addr);
                mma_f16(oS, pa, bs);
            }
        }
    }

    float s0 = __shfl_sync(0xffffffffu, oS[0], lane & 28);
    float s1 = __shfl_sync(0xffffffffu, oS[2], lane & 28);
    const float inv0 = 1.f / s0;
    const float inv1 = 1.f / s1;

    const int t0 = h128 + qrow0 + lq;
#pragma unroll
    for (int dn = 0; dn < 8; dn++) {
        int d = (dn << 3) + lc;
        __half2 h0 = __floats2half2_rn(o[dn][0] * inv0, o[dn][1] * inv0);
        __half2 h1 = __floats2half2_rn(o[dn][2] * inv1, o[dn][3] * inv1);
        size_t ob0 = ((size_t)b * 512 + (2 * t0 + lpar)) * 1024
                   + (size_t)g * 512 + cbase + d;
        size_t ob1 = ((size_t)b * 512 + (2 * (t0 + 8) + lpar)) * 1024
                   + (size_t)g * 512 + cbase + d;
        *(__half2*)&atted[ob0] = h0;
        *(__half2*)&atted[ob1] = h1;
    }
}

// ---------------------------------------------------------------------------
// Residual-add + LayerNorm over rows of 1024. One block (256 thr) per row.
// dlt may be fp32 or half (dlt_half flag).
// ---------------------------------------------------------------------------
__global__ __launch_bounds__(256)
void add_ln_kernel(const float* __restrict__ res, const void* __restrict__ dlt,
                   int dlt_half,
                   const float* __restrict__ gamma, const float* __restrict__ beta,
                   float* __restrict__ out, __half* __restrict__ outh)
{
    __shared__ float red[8];
    __shared__ float s_mean, s_inv;
    const int row = blockIdx.x;
    const int tid = threadIdx.x;
    const size_t base = (size_t)row * 1024;
    const int c0 = tid << 2;

    float4 xr = *(const float4*)&res[base + c0];
    float xd[4];
    if (dlt_half) {
        const __half2* dh = (const __half2*)((const __half*)dlt + base + c0);
        float2 d0 = __half22float2(dh[0]);
        float2 d1 = __half22float2(dh[1]);
        xd[0] = d0.x; xd[1] = d0.y; xd[2] = d1.x; xd[3] = d1.y;
    } else {
        float4 df = *(const float4*)((const float*)dlt + base + c0);
        xd[0] = df.x; xd[1] = df.y; xd[2] = df.z; xd[3] = df.w;
    }
    float x[4] = { xr.x + xd[0], xr.y + xd[1], xr.z + xd[2], xr.w + xd[3] };
    float s = x[0] + x[1] + x[2] + x[3];
#pragma unroll
    for (int o = 16; o; o >>= 1) s += __shfl_xor_sync(0xffffffffu, s, o);
    if ((tid & 31) == 0) red[tid >> 5] = s;
    __syncthreads();
    if (tid < 32) {
        float t = (tid < 8) ? red[tid] : 0.f;
#pragma unroll
        for (int o = 4; o; o >>= 1) t += __shfl_xor_sync(0xffffffffu, t, o);
        if (tid == 0) s_mean = t * (1.f / 1024.f);
    }
    __syncthreads();
    const float mean = s_mean;

    float vs = 0.f;
#pragma unroll
    for (int i = 0; i < 4; i++) { float d = x[i] - mean; vs += d * d; }
#pragma unroll
    for (int o = 16; o; o >>= 1) vs += __shfl_xor_sync(0xffffffffu, vs, o);
    if ((tid & 31) == 0) red[tid >> 5] = vs;
    __syncthreads();
    if (tid < 32) {
        float t = (tid < 8) ? red[tid] : 0.f;
#pragma unroll
        for (int o = 4; o; o >>= 1) t += __shfl_xor_sync(0xffffffffu, t, o);
        if (tid == 0) s_inv = rsqrtf(t * (1.f / 1024.f) + 1e-6f);
    }
    __syncthreads();
    const float inv = s_inv;

    float4 gm = *(const float4*)&gamma[c0];
    float4 bt = *(const float4*)&beta[c0];
    float4 o4;
    o4.x = (x[0] - mean) * inv * gm.x + bt.x;
    o4.y = (x[1] - mean) * inv * gm.y + bt.y;
    o4.z = (x[2] - mean) * inv * gm.z + bt.z;
    o4.w = (x[3] - mean) * inv * gm.w + bt.w;
    *(float4*)&out[base + c0] = o4;
    if (outh) {
        __half2 h0 = __floats2half2_rn(o4.x, o4.y);
        __half2 h1 = __floats2half2_rn(o4.z, o4.w);
        *(__half2*)&outh[base + c0]     = h0;
        *(__half2*)&outh[base + c0 + 2] = h1;
    }
}

// ---------------------------------------------------------------------------
// Launch.  8 kernels total.
// ---------------------------------------------------------------------------
extern "C" void kernel_launch(void* const* d_in, const int* in_sizes, int n_in,
                              void* d_out, int out_size)
{
    const float* y   = (const float*)d_in[0];
    const void*  msk = d_in[1];
    const float* Wv  = (const float*)d_in[2];
    const float* bv  = (const float*)d_in[3];
    const float* Wk  = (const float*)d_in[4];
    const float* bk  = (const float*)d_in[5];
    const float* Wq  = (const float*)d_in[6];
    const float* bq  = (const float*)d_in[7];
    const float* Wm  = (const float*)d_in[8];
    const float* bm  = (const float*)d_in[9];
    const float* W1  = (const float*)d_in[10];
    const float* b1  = (const float*)d_in[11];
    const float* W2  = (const float*)d_in[12];
    const float* b2  = (const float*)d_in[13];
    const float* g1  = (const float*)d_in[14];
    const float* be1 = (const float*)d_in[15];
    const float* g2  = (const float*)d_in[16];
    const float* be2 = (const float*)d_in[17];
    float* out = (float*)d_out;

    __half *yh, *wqkvT, *wmT, *w1T, *w2T, *qkv, *att, *y1h, *h1, *mh, *ff;
    float *bqkv, *y1;
    cudaGetSymbolAddress((void**)&yh,    g_yh);
    cudaGetSymbolAddress((void**)&wqkvT, g_wqkvT);
    cudaGetSymbolAddress((void**)&bqkv,  g_bqkv);
    cudaGetSymbolAddress((void**)&wmT,   g_wmT);
    cudaGetSymbolAddress((void**)&w1T,   g_w1T);
    cudaGetSymbolAddress((void**)&w2T,   g_w2T);
    cudaGetSymbolAddress((void**)&qkv,   g_qkv);
    cudaGetSymbolAddress((void**)&att,   g_att);
    cudaGetSymbolAddress((void**)&mh,    g_mh);
    cudaGetSymbolAddress((void**)&y1,    g_y1);
    cudaGetSymbolAddress((void**)&y1h,   g_y1h);
    cudaGetSymbolAddress((void**)&h1,    g_h1);
    cudaGetSymbolAddress((void**)&ff,    g_ff);

    cudaFuncSetAttribute(attn_mma,
                         cudaFuncAttributeMaxDynamicSharedMemorySize, ATTN_SMEM_BYTES);
    cudaFuncSetAttribute(hgemm<true,  false, true >,
                         cudaFuncAttributeMaxDynamicSharedMemorySize, GEMM_SMEM_BYTES);
    cudaFuncSetAttribute(hgemm<false, false, true >,
                         cudaFuncAttributeMaxDynamicSharedMemorySize, GEMM_SMEM_BYTES);
    cudaFuncSetAttribute(hgemm<false, true,  true >,
                         cudaFuncAttributeMaxDynamicSharedMemorySize, GEMM_SMEM_BYTES);

    dim3 blk(256);

    // 1) fused pre-pass
    prep<<<7937, blk>>>(y, yh, Wq, Wk, Wv, wqkvT, Wm, wmT, W1, w1T, W2, w2T,
                        bq, bk, bv, bqkv);

    // 2) Fused QKV: (16384,1536) = gather(yh) @ Wqkv + bqkv -> half
    hgemm<true,  false, true ><<<dim3(12, 128), blk, GEMM_SMEM_BYTES>>>(yh, wqkvT, bqkv, qkv, 16384, 1536, 512);

    // 3) Flash tensor-core attention -> att (half, B,L,H layout)
    attn_mma<<<1024, ATTN_THREADS, ATTN_SMEM_BYTES>>>(qkv, msk, att);

    // 4) Merge: (8192,1024) @ Wm + bm -> half
    hgemm<false, false, true ><<<dim3(8, 64), blk, GEMM_SMEM_BYTES>>>(att, wmT, bm, mh, 8192, 1024, 1024);

    // 5) y1 = LN(y + merge): fp32 (residual) + half (FFN1 input)
    add_ln_kernel<<<8192, blk>>>(y, mh, 1, g1, be1, y1, y1h);

    // 6) FFN1: (8192,1024) @ W1 + b1, relu -> half
    hgemm<false, true,  true ><<<dim3(32, 64), blk, GEMM_SMEM_BYTES>>>(y1h, w1T, b1, h1, 8192, 4096, 1024);

    // 7) FFN2: (16384,2048) @ W2 + b2 -> half
    hgemm<false, false, true ><<<dim3(4, 128), blk, GEMM_SMEM_BYTES>>>(h1, w2T, b2, ff, 16384, 512, 2048);

    // 8) out = LN(y1 + ff), full fp32
    add_ln_kernel<<<8192, blk>>>(y1, ff, 1, g2, be2, out, (__half*)0);
}

// round 16
// speedup vs baseline: 1.2594x; 1.0210x over previous
#include <cuda_runtime.h>
#include <cuda_fp16.h>
#include <math.h>
#include <stdint.h>

// ---------------------------------------------------------------------------
// Problem constants: B=16, L=512, H=1024, G=2, NH=16, DH=64, FF=4096,
//                    DM=512, LG=256
// ---------------------------------------------------------------------------

// Scratch (device globals; allocation inside kernel_launch is forbidden)
__device__ __half g_yh   [16u*512u*1024u];
__device__ __half g_wqkvT[1536u*512u];
__device__ float  g_bqkv [1536u];
__device__ __half g_wmT  [1024u*1024u];
__device__ __half g_w1T  [4096u*1024u];
__device__ __half g_w2T  [512u*2048u];
__device__ __half g_qkv  [16384u*1536u];
__device__ __half g_att  [16u*512u*1024u];
__device__ __half g_mh   [16u*512u*1024u];
__device__ float  g_y1   [16u*512u*1024u];
__device__ __half g_y1h  [16u*512u*1024u];
__device__ __half g_h1   [8192u*4096u];
__device__ __half g_ff   [16u*512u*1024u];

// ---------------------------------------------------------------------------
// Helpers
// ---------------------------------------------------------------------------
__device__ __forceinline__ void mma_f16(float* d, const unsigned* a, const unsigned* b) {
    asm volatile(
        "mma.sync.aligned.m16n8k16.row.col.f32.f16.f16.f32 "
        "{%0,%1,%2,%3}, {%4,%5,%6,%7}, {%8,%9}, {%0,%1,%2,%3};\n"
        : "+f"(d[0]), "+f"(d[1]), "+f"(d[2]), "+f"(d[3])
        : "r"(a[0]), "r"(a[1]), "r"(a[2]), "r"(a[3]), "r"(b[0]), "r"(b[1]));
}

__device__ __forceinline__ void ldsm_x4(unsigned* r, unsigned a) {
    asm volatile("ldmatrix.sync.aligned.m8n8.x4.shared.b16 {%0,%1,%2,%3}, [%4];"
        : "=r"(r[0]), "=r"(r[1]), "=r"(r[2]), "=r"(r[3]) : "r"(a));
}
__device__ __forceinline__ void ldsm_x4_t(unsigned* r, unsigned a) {
    asm volatile("ldmatrix.sync.aligned.m8n8.x4.trans.shared.b16 {%0,%1,%2,%3}, [%4];"
        : "=r"(r[0]), "=r"(r[1]), "=r"(r[2]), "=r"(r[3]) : "r"(a));
}
__device__ __forceinline__ void ldsm_x2_t(unsigned* r, unsigned a) {
    asm volatile("ldmatrix.sync.aligned.m8n8.x2.trans.shared.b16 {%0,%1}, [%2];"
        : "=r"(r[0]), "=r"(r[1]) : "r"(a));
}
__device__ __forceinline__ unsigned ex2_h2(unsigned x) {
    unsigned y;
    asm volatile("ex2.approx.f16x2 %0, %1;" : "=r"(y) : "r"(x));
    return y;
}

__device__ __forceinline__ void cp16(unsigned dst, const void* src) {
    asm volatile("cp.async.cg.shared.global [%0], [%1], 16;\n" :: "r"(dst), "l"(src));
}
__device__ __forceinline__ void cp_commit() {
    asm volatile("cp.async.commit_group;\n" ::);
}
template<int N>
__device__ __forceinline__ void cp_wait() {
    asm volatile("cp.async.wait_group %0;\n" :: "n"(N));
}

// ---------------------------------------------------------------------------
// Fused pre-pass (unchanged): weight transposes (+half), y->half, bias pack.
// ---------------------------------------------------------------------------
__device__ __forceinline__ void transp_tile(const float* __restrict__ in,
                                            __half* __restrict__ out,
                                            int K, int N, int nb, int kb,
                                            float (*t)[33], int tid)
{
    int tx = tid & 31, ty = tid >> 5;
#pragma unroll
    for (int i = 0; i < 32; i += 8)
        t[ty + i][tx] = in[(size_t)(kb + ty + i) * N + nb + tx];
    __syncthreads();
#pragma unroll
    for (int i = 0; i < 32; i += 8)
        out[(size_t)(nb + ty + i) * K + kb + tx] = __float2half(t[tx][ty + i]);
}

__global__ __launch_bounds__(256)
void prep(const float* __restrict__ y, __half* __restrict__ yh,
          const float* __restrict__ Wq, const float* __restrict__ Wk,
          const float* __restrict__ Wv, __half* __restrict__ wqkvT,
          const float* __restrict__ Wm, __half* __restrict__ wmT,
          const float* __restrict__ W1, __half* __restrict__ w1T,
          const float* __restrict__ W2, __half* __restrict__ w2T,
          const float* __restrict__ bq, const float* __restrict__ bk,
          const float* __restrict__ bv, float* __restrict__ bqkv)
{
    __shared__ float t[32][33];
    const int bid = blockIdx.x;
    const int tid = threadIdx.x;

    if (bid < 768) {
        int nbt = bid % 48, kbt = bid / 48;
        int nb = nbt << 5, kb = kbt << 5;
        const float* src = (nb < 512) ? Wq : (nb < 1024) ? Wk : Wv;
        int nloc = nb & 511;
        int tx = tid & 31, ty = tid >> 5;
#pragma unroll
        for (int i = 0; i < 32; i += 8)
            t[ty + i][tx] = src[(size_t)(kb + ty + i) * 512 + nloc + tx];
        __syncthreads();
#pragma unroll
        for (int i = 0; i < 32; i += 8)
            wqkvT[(size_t)(nb + ty + i) * 512 + kb + tx] = __float2half(t[tx][ty + i]);
    } else if (bid < 1792) {
        int r = bid - 768;
        transp_tile(Wm, wmT, 1024, 1024, (r % 32) << 5, (r / 32) << 5, t, tid);
    } else if (bid < 5888) {
        int r = bid - 1792;
        transp_tile(W1, w1T, 1024, 4096, (r % 128) << 5, (r / 128) << 5, t, tid);
    } else if (bid < 6912) {
        int r = bid - 5888;
        transp_tile(W2, w2T, 2048, 512, (r % 16) << 5, (r / 16) << 5, t, tid);
    } else if (bid < 7936) {
        size_t base = (size_t)(bid - 6912) * 8192 + (tid << 2);
#pragma unroll
        for (int j = 0; j < 8; j++) {
            size_t idx = base + (size_t)j * 1024;
            float4 v = *(const float4*)&y[idx];
            __half2 h0 = __floats2half2_rn(v.x, v.y);
            __half2 h1 = __floats2half2_rn(v.z, v.w);
            *(__half2*)&yh[idx]     = h0;
            *(__half2*)&yh[idx + 2] = h1;
        }
    } else {
#pragma unroll
        for (int j = 0; j < 6; j++) {
            int i = tid + (j << 8);
            int s = i >> 9, c = i & 511;
            const float* bs = (s == 0) ? bq : (s == 1) ? bk : bv;
            bqkv[i] = bs[c];
        }
    }
}

// ---------------------------------------------------------------------------
// fp16 tensor-core GEMM — R15 config (K-step 64, XOR swizzle, 3-stage,
// 2 CTAs/SM).  Unchanged.
// ---------------------------------------------------------------------------
#define STAGES 3
#define TILE_BYTES 16384
#define STAGE_BYTES (2 * TILE_BYTES)
#define GEMM_SMEM_BYTES (STAGES * STAGE_BYTES)  // 98304

#define GEMM_ISSUE(s_) do {                                                   \
    int ko_ = (s_) << 6;                                                      \
    unsigned sb_ = sbase + (unsigned)(((s_) % STAGES) * STAGE_BYTES);         \
    _Pragma("unroll")                                                         \
    for (int i_ = 0; i_ < 4; i_++)                                            \
        cp16(sb_ + a_sm0 + (unsigned)(i_ << 12),                              \
             a_gm0 + (size_t)i_ * a_str + ko_);                               \
    _Pragma("unroll")                                                         \
    for (int i_ = 0; i_ < 4; i_++)                                            \
        cp16(sb_ + TILE_BYTES + a_sm0 + (unsigned)(i_ << 12),                 \
             b_gm0 + (size_t)(i_ << 5) * (size_t)K + ko_);                    \
} while (0)

template<bool GATHER_A, bool RELU, bool OUT_HALF>
__global__ __launch_bounds__(256, 2)
void hgemm(const __half* __restrict__ A, const __half* __restrict__ BT,
           const float* __restrict__ bias, void* __restrict__ Cv,
           int M, int N, int K)
{
    extern __shared__ unsigned char dsm[];
    const unsigned sbase = (unsigned)__cvta_generic_to_shared(dsm);

    const int tid  = threadIdx.x;
    const int row0 = blockIdx.y << 7;
    const int col0 = blockIdx.x << 7;
    const int lane = tid & 31;
    const int w    = tid >> 5;
    const int wm   = w & 1;
    const int wn   = w >> 1;
    const int tig  = lane & 3;
    const int grp  = lane >> 2;
    const int lo7  = lane & 7;

    const int cr = tid >> 3;
    const int lc = tid & 7;
    const unsigned a_sm0 = (unsigned)((cr << 7) + ((lc ^ (cr & 7)) << 4));
    const int kc0 = lc << 3;
    const __half* a_gm0;
    size_t a_str;
    if (GATHER_A) {
        int grow = row0 + cr;
        int bg = grow >> 9, l = grow & 511;
        int b  = bg & 15,  g = bg >> 4;
        a_gm0 = A + (((size_t)b * 512 + l) * 1024 + (size_t)g * 512) + kc0;
        a_str = (size_t)32 * 1024;
    } else {
        a_gm0 = A + (size_t)(row0 + cr) * (size_t)K + kc0;
        a_str = (size_t)32 * (size_t)K;
    }
    const __half* b_gm0 = BT + (size_t)(col0 + cr) * (size_t)K + kc0;

    const unsigned a_base = (unsigned)(((wm << 6) + (lane & 15)) << 7);
    unsigned a_ck[4];
#pragma unroll
    for (int ks = 0; ks < 4; ks++)
        a_ck[ks] = (unsigned)((((ks << 1) + (lane >> 4)) ^ lo7) << 4);
    const unsigned b_base = (unsigned)(((wn << 5) + lo7) << 7);
    unsigned b_ck[2];
#pragma unroll
    for (int j = 0; j < 2; j++)
        b_ck[j] = (unsigned)((((j << 2) + ((lane >> 3) & 3)) ^ lo7) << 4);

    float acc[4][4][4];
#pragma unroll
    for (int mi = 0; mi < 4; mi++)
#pragma unroll
        for (int ni = 0; ni < 4; ni++)
#pragma unroll
            for (int j = 0; j < 4; j++) acc[mi][ni][j] = 0.f;

    GEMM_ISSUE(0); cp_commit();
    GEMM_ISSUE(1); cp_commit();

    const int nIter = K >> 6;
    for (int it = 0; it < nIter; ++it) {
        cp_wait<1>();
        __syncthreads();

        const unsigned stg  = sbase + (unsigned)((it % STAGES) * STAGE_BYTES);
        const unsigned stgB = stg + TILE_BYTES;

        unsigned bf[4][4];
#pragma unroll
        for (int ks = 0; ks < 4; ks++) {
            if ((ks & 1) == 0) {
#pragma unroll
                for (int ni = 0; ni < 4; ni++)
                    ldsm_x4(bf[ni], stgB + b_base + (unsigned)(ni << 10)
                                  + b_ck[ks >> 1]);
            }
            unsigned af[4][4];
#pragma unroll
            for (int mi = 0; mi < 4; mi++)
                ldsm_x4(af[mi], stg + a_base + (unsigned)(mi << 11) + a_ck[ks]);
#pragma unroll
            for (int mi = 0; mi < 4; mi++)
#pragma unroll
                for (int ni = 0; ni < 4; ni++)
                    mma_f16(acc[mi][ni], af[mi], &bf[ni][(ks & 1) << 1]);
        }

        int s = it + 2;
        if (s < nIter) GEMM_ISSUE(s);
        cp_commit();
    }

#pragma unroll
    for (int mi = 0; mi < 4; mi++) {
        int r = row0 + (wm << 6) + (mi << 4) + grp;
#pragma unroll
        for (int ni = 0; ni < 4; ni++) {
            int c = col0 + (wn << 5) + (ni << 3) + (tig << 1);
            float2 bv = *(const float2*)&bias[c];
            float v00 = acc[mi][ni][0] + bv.x;
            float v01 = acc[mi][ni][1] + bv.y;
            float v10 = acc[mi][ni][2] + bv.x;
            float v11 = acc[mi][ni][3] + bv.y;
            if (RELU) {
                v00 = fmaxf(v00, 0.f); v01 = fmaxf(v01, 0.f);
                v10 = fmaxf(v10, 0.f); v11 = fmaxf(v11, 0.f);
            }
            if (OUT_HALF) {
                __half* Ch = (__half*)Cv;
                *(__half2*)&Ch[(size_t)r * N + c]       = __floats2half2_rn(v00, v01);
                *(__half2*)&Ch[(size_t)(r + 8) * N + c] = __floats2half2_rn(v10, v11);
            } else {
                float* Cf = (float*)Cv;
                float2 o0; o0.x = v00; o0.y = v01;
                float2 o1; o1.x = v10; o1.y = v11;
                *(float2*)&Cf[(size_t)r * N + c]       = o0;
                *(float2*)&Cf[(size_t)(r + 8) * N + c] = o1;
            }
        }
    }
}

// ---------------------------------------------------------------------------
// Flash tensor-core attention with PIPELINED cp.async chunk loads:
//   group A = Q + K0 + V0 (first 128 keys), group B = K1 + V1.
//   compute chunk 0 after wait<1> (group B still in flight), chunk 1 after
//   wait<0>.  exp2-h2 softmax + ones-column row sums (R14/15).
// Grid = 1024 = (bg, head, q-half), 256 threads, 2 CTAs/SM.
// ---------------------------------------------------------------------------
#define ATTN_THREADS 256
#define QKV_STRIDE 1536
#define QP 72
#define ATTN_SMEM_BYTES ((128 + 256 + 256) * QP * 2)   // 92160
#define LOG2E 1.4426950408889634f

__global__ __launch_bounds__(ATTN_THREADS, 2)
void attn_mma(const __half* __restrict__ qkv, const void* __restrict__ maskp,
              __half* __restrict__ atted)
{
    extern __shared__ __half hs[];
    __half* Qs = hs;                 // 128 x QP
    __half* Ks = Qs + 128 * QP;      // 256 x QP
    __half* Vs = Ks + 256 * QP;      // 256 x QP
    __shared__ float mvals[256];

    const int bh   = blockIdx.x >> 1;
    const int qh   = blockIdx.x & 1;
    const int bg   = bh >> 4;
    const int h    = bh & 15;
    const int tid  = threadIdx.x;
    const int lane = tid & 31;
    const int w    = tid >> 5;
    const int lpar  = h >> 3;
    const int cbase = (h & 7) << 6;
    const int b = bg & 15;
    const int g = bg >> 4;
    const int h128 = qh << 7;

    // mask dtype detection (needs an early barrier anyway)
    unsigned word = ((const unsigned*)maskp)[tid];
    int is32 = __syncthreads_and(word <= 1u);

    const __half* base = qkv + (size_t)bg * 512 * QKV_STRIDE;
    const unsigned qs0 = (unsigned)__cvta_generic_to_shared(Qs);
    const unsigned ks0 = (unsigned)__cvta_generic_to_shared(Ks);
    const unsigned vs0 = (unsigned)__cvta_generic_to_shared(Vs);

    // per-thread cp mapping: t = tid>>3 (+128 j-steps), d8 = (tid&7)*8
    const int ct  = tid >> 3;           // 0..31
    const int d8  = (tid & 7) << 3;     // 0..56
    const unsigned soff = (unsigned)(d8 << 1);  // byte offset within row

    // --- group A: Q (this q-half) + K0 + V0 ---
#pragma unroll
    for (int j = 0; j < 4; j++) {       // Q rows ct + 32j  (0..127)
        int t = ct + (j << 5);
        size_t off = (size_t)(2 * (h128 + t) + lpar) * QKV_STRIDE + cbase + d8;
        cp16(qs0 + (unsigned)(t * (QP * 2)) + soff, base + off);
    }
#pragma unroll
    for (int j = 0; j < 4; j++) {       // K0/V0 rows ct + 32j (0..127)
        int t = ct + (j << 5);
        size_t off = (size_t)(2 * t + lpar) * QKV_STRIDE + cbase + d8;
        cp16(ks0 + (unsigned)(t * (QP * 2)) + soff, base + 512 + off);
        cp16(vs0 + (unsigned)(t * (QP * 2)) + soff, base + 1024 + off);
    }
    cp_commit();
    // --- group B: K1 + V1 ---
#pragma unroll
    for (int j = 0; j < 4; j++) {       // rows 128 + ct + 32j (128..255)
        int t = 128 + ct + (j << 5);
        size_t off = (size_t)(2 * t + lpar) * QKV_STRIDE + cbase + d8;
        cp16(ks0 + (unsigned)(t * (QP * 2)) + soff, base + 512 + off);
        cp16(vs0 + (unsigned)(t * (QP * 2)) + soff, base + 1024 + off);
    }
    cp_commit();

    // ones column in V padding (col 64 = 1.0h) + log2-domain mask
    {
        uint4 ones = {0x00003C00u, 0u, 0u, 0u};
        *(uint4*)&Vs[tid * QP + 64] = ones;
        int mv = is32 ? ((const int*)maskp)[b * 256 + tid]
                      : (int)((const unsigned char*)maskp)[b * 256 + tid];
        mvals[tid] = mv ? (-1e9f * LOG2E) : 0.0f;
    }

    const int lq = lane >> 2;
    const int lc = (lane & 3) << 1;
    const int qrow0 = w << 4;

    const float scale = 0.125f * LOG2E;
    float m0 = -3.0e38f, m1 = -3.0e38f;
    float o[8][4];
    float oS[4];
#pragma unroll
    for (int dn = 0; dn < 8; dn++) {
        o[dn][0] = 0.f; o[dn][1] = 0.f; o[dn][2] = 0.f; o[dn][3] = 0.f;
    }
    oS[0] = 0.f; oS[1] = 0.f; oS[2] = 0.f; oS[3] = 0.f;

    unsigned aq[4][4];

#pragma unroll 1
    for (int c = 0; c < 2; c++) {
        if (c == 0) { cp_wait<1>(); __syncthreads(); }   // Q,K0,V0 ready
        else        { cp_wait<0>(); __syncthreads(); }   // K1,V1 ready
        const int kbase = c << 7;

        if (c == 0) {
#pragma unroll
            for (int ks = 0; ks < 4; ks++) {
                unsigned addr = qs0 + (unsigned)(((qrow0 + (lane & 15)) * QP
                                  + (ks << 4) + ((lane >> 4) << 3)) * 2);
                ldsm_x4(aq[ks], addr);
            }
        }

        float acc[16][4];
#pragma unroll
        for (int nt = 0; nt < 16; nt++) {
            acc[nt][0] = 0.f; acc[nt][1] = 0.f; acc[nt][2] = 0.f; acc[nt][3] = 0.f;
            unsigned bk[2][4];
#pragma unroll
            for (int j = 0; j < 2; j++) {
                unsigned addr = ks0 + (unsigned)(((kbase + (nt << 3) + (lane & 7)) * QP
                                  + (j << 5) + ((lane >> 3) << 3)) * 2);
                ldsm_x4(bk[j], addr);
            }
            mma_f16(acc[nt], aq[0], &bk[0][0]);
            mma_f16(acc[nt], aq[1], &bk[0][2]);
            mma_f16(acc[nt], aq[2], &bk[1][0]);
            mma_f16(acc[nt], aq[3], &bk[1][2]);
        }

        float cm0 = -3.0e38f, cm1 = -3.0e38f;
#pragma unroll
        for (int nt = 0; nt < 16; nt++) {
            float mv0 = mvals[kbase + (nt << 3) + lc];
            float mv1 = mvals[kbase + (nt << 3) + lc + 1];
            acc[nt][0] = acc[nt][0] * scale + mv0;
            acc[nt][1] = acc[nt][1] * scale + mv1;
            acc[nt][2] = acc[nt][2] * scale + mv0;
            acc[nt][3] = acc[nt][3] * scale + mv1;
            cm0 = fmaxf(cm0, fmaxf(acc[nt][0], acc[nt][1]));
            cm1 = fmaxf(cm1, fmaxf(acc[nt][2], acc[nt][3]));
        }
        cm0 = fmaxf(cm0, __shfl_xor_sync(0xffffffffu, cm0, 1));
        cm0 = fmaxf(cm0, __shfl_xor_sync(0xffffffffu, cm0, 2));
        cm1 = fmaxf(cm1, __shfl_xor_sync(0xffffffffu, cm1, 1));
        cm1 = fmaxf(cm1, __shfl_xor_sync(0xffffffffu, cm1, 2));

        float nm0 = fmaxf(m0, cm0);
        float nm1 = fmaxf(m1, cm1);
        float f0 = exp2f(m0 - nm0);
        float f1 = exp2f(m1 - nm1);
        m0 = nm0; m1 = nm1;
#pragma unroll
        for (int dn = 0; dn < 8; dn++) {
            o[dn][0] *= f0; o[dn][1] *= f0;
            o[dn][2] *= f1; o[dn][3] *= f1;
        }
        oS[0] *= f0; oS[1] *= f0; oS[2] *= f1; oS[3] *= f1;

        unsigned P[16][2];
#pragma unroll
        for (int nt = 0; nt < 16; nt++) {
            __half2 x01 = __floats2half2_rn(acc[nt][0] - m0, acc[nt][1] - m0);
            __half2 x23 = __floats2half2_rn(acc[nt][2] - m1, acc[nt][3] - m1);
            P[nt][0] = ex2_h2(*(unsigned*)&x01);
            P[nt][1] = ex2_h2(*(unsigned*)&x23);
        }

#pragma unroll
        for (int kt = 0; kt < 8; kt++) {
            unsigned pa[4];
            pa[0] = P[2*kt][0];   pa[1] = P[2*kt][1];
            pa[2] = P[2*kt+1][0]; pa[3] = P[2*kt+1][1];
#pragma unroll
            for (int p = 0; p < 4; p++) {
                unsigned bv[4];
                unsigned addr = vs0 + (unsigned)(((kbase + (kt << 4)
                                  + ((lane >> 3) & 1) * 8 + (lane & 7)) * QP
                                  + (p << 4) + ((lane >> 4) << 3)) * 2);
                ldsm_x4_t(bv, addr);
                mma_f16(o[2*p],     pa, &bv[0]);
                mma_f16(o[2*p + 1], pa, &bv[2]);
            }
            {
                unsigned bs[2];
                unsigned addr = vs0 + (unsigned)(((kbase + (kt << 4)
                                  + (lane & 15)) * QP + 64) * 2);
                ldsm_x2_t(bs, addr);
                mma_f16(oS, pa, bs);
            }
        }
    }

    float s0 = __shfl_sync(0xffffffffu, oS[0], lane & 28);
    float s1 = __shfl_sync(0xffffffffu, oS[2], lane & 28);
    const float inv0 = 1.f / s0;
    const float inv1 = 1.f / s1;

    const int t0 = h128 + qrow0 + lq;
#pragma unroll
    for (int dn = 0; dn < 8; dn++) {
        int d = (dn << 3) + lc;
        __half2 h0 = __floats2half2_rn(o[dn][0] * inv0, o[dn][1] * inv0);
        __half2 h1 = __floats2half2_rn(o[dn][2] * inv1, o[dn][3] * inv1);
        size_t ob0 = ((size_t)b * 512 + (2 * t0 + lpar)) * 1024
                   + (size_t)g * 512 + cbase + d;
        size_t ob1 = ((size_t)b * 512 + (2 * (t0 + 8) + lpar)) * 1024
                   + (size_t)g * 512 + cbase + d;
        *(__half2*)&atted[ob0] = h0;
        *(__half2*)&atted[ob1] = h1;
    }
}

// ---------------------------------------------------------------------------
// Residual-add + LayerNorm over rows of 1024. One block (256 thr) per row.
// dlt may be fp32 or half (dlt_half flag).
// ---------------------------------------------------------------------------
__global__ __launch_bounds__(256)
void add_ln_kernel(const float* __restrict__ res, const void* __restrict__ dlt,
                   int dlt_half,
                   const float* __restrict__ gamma, const float* __restrict__ beta,
                   float* __restrict__ out, __half* __restrict__ outh)
{
    __shared__ float red[8];
    __shared__ float s_mean, s_inv;
    const int row = blockIdx.x;
    const int tid = threadIdx.x;
    const size_t base = (size_t)row * 1024;
    const int c0 = tid << 2;

    float4 xr = *(const float4*)&res[base + c0];
    float xd[4];
    if (dlt_half) {
        const __half2* dh = (const __half2*)((const __half*)dlt + base + c0);
        float2 d0 = __half22float2(dh[0]);
        float2 d1 = __half22float2(dh[1]);
        xd[0] = d0.x; xd[1] = d0.y; xd[2] = d1.x; xd[3] = d1.y;
    } else {
        float4 df = *(const float4*)((const float*)dlt + base + c0);
        xd[0] = df.x; xd[1] = df.y; xd[2] = df.z; xd[3] = df.w;
    }
    float x[4] = { xr.x + xd[0], xr.y + xd[1], xr.z + xd[2], xr.w + xd[3] };
    float s = x[0] + x[1] + x[2] + x[3];
#pragma unroll
    for (int o = 16; o; o >>= 1) s += __shfl_xor_sync(0xffffffffu, s, o);
    if ((tid & 31) == 0) red[tid >> 5] = s;
    __syncthreads();
    if (tid < 32) {
        float t = (tid < 8) ? red[tid] : 0.f;
#pragma unroll
        for (int o = 4; o; o >>= 1) t += __shfl_xor_sync(0xffffffffu, t, o);
        if (tid == 0) s_mean = t * (1.f / 1024.f);
    }
    __syncthreads();
    const float mean = s_mean;

    float vs = 0.f;
#pragma unroll
    for (int i = 0; i < 4; i++) { float d = x[i] - mean; vs += d * d; }
#pragma unroll
    for (int o = 16; o; o >>= 1) vs += __shfl_xor_sync(0xffffffffu, vs, o);
    if ((tid & 31) == 0) red[tid >> 5] = vs;
    __syncthreads();
    if (tid < 32) {
        float t = (tid < 8) ? red[tid] : 0.f;
#pragma unroll
        for (int o = 4; o; o >>= 1) t += __shfl_xor_sync(0xffffffffu, t, o);
        if (tid == 0) s_inv = rsqrtf(t * (1.f / 1024.f) + 1e-6f);
    }
    __syncthreads();
    const float inv = s_inv;

    float4 gm = *(const float4*)&gamma[c0];
    float4 bt = *(const float4*)&beta[c0];
    float4 o4;
    o4.x = (x[0] - mean) * inv * gm.x + bt.x;
    o4.y = (x[1] - mean) * inv * gm.y + bt.y;
    o4.z = (x[2] - mean) * inv * gm.z + bt.z;
    o4.w = (x[3] - mean) * inv * gm.w + bt.w;
    *(float4*)&out[base + c0] = o4;
    if (outh) {
        __half2 h0 = __floats2half2_rn(o4.x, o4.y);
        __half2 h1 = __floats2half2_rn(o4.z, o4.w);
        *(__half2*)&outh[base + c0]     = h0;
        *(__half2*)&outh[base + c0 + 2] = h1;
    }
}

// ---------------------------------------------------------------------------
// Launch.  8 kernels total.
// ---------------------------------------------------------------------------
extern "C" void kernel_launch(void* const* d_in, const int* in_sizes, int n_in,
                              void* d_out, int out_size)
{
    const float* y   = (const float*)d_in[0];
    const void*  msk = d_in[1];
    const float* Wv  = (const float*)d_in[2];
    const float* bv  = (const float*)d_in[3];
    const float* Wk  = (const float*)d_in[4];
    const float* bk  = (const float*)d_in[5];
    const float* Wq  = (const float*)d_in[6];
    const float* bq  = (const float*)d_in[7];
    const float* Wm  = (const float*)d_in[8];
    const float* bm  = (const float*)d_in[9];
    const float* W1  = (const float*)d_in[10];
    const float* b1  = (const float*)d_in[11];
    const float* W2  = (const float*)d_in[12];
    const float* b2  = (const float*)d_in[13];
    const float* g1  = (const float*)d_in[14];
    const float* be1 = (const float*)d_in[15];
    const float* g2  = (const float*)d_in[16];
    const float* be2 = (const float*)d_in[17];
    float* out = (float*)d_out;

    __half *yh, *wqkvT, *wmT, *w1T, *w2T, *qkv, *att, *y1h, *h1, *mh, *ff;
    float *bqkv, *y1;
    cudaGetSymbolAddress((void**)&yh,    g_yh);
    cudaGetSymbolAddress((void**)&wqkvT, g_wqkvT);
    cudaGetSymbolAddress((void**)&bqkv,  g_bqkv);
    cudaGetSymbolAddress((void**)&wmT,   g_wmT);
    cudaGetSymbolAddress((void**)&w1T,   g_w1T);
    cudaGetSymbolAddress((void**)&w2T,   g_w2T);
    cudaGetSymbolAddress((void**)&qkv,   g_qkv);
    cudaGetSymbolAddress((void**)&att,   g_att);
    cudaGetSymbolAddress((void**)&mh,    g_mh);
    cudaGetSymbolAddress((void**)&y1,    g_y1);
    cudaGetSymbolAddress((void**)&y1h,   g_y1h);
    cudaGetSymbolAddress((void**)&h1,    g_h1);
    cudaGetSymbolAddress((void**)&ff,    g_ff);

    cudaFuncSetAttribute(attn_mma,
                         cudaFuncAttributeMaxDynamicSharedMemorySize, ATTN_SMEM_BYTES);
    cudaFuncSetAttribute(hgemm<true,  false, true >,
                         cudaFuncAttributeMaxDynamicSharedMemorySize, GEMM_SMEM_BYTES);
    cudaFuncSetAttribute(hgemm<false, false, true >,
                         cudaFuncAttributeMaxDynamicSharedMemorySize, GEMM_SMEM_BYTES);
    cudaFuncSetAttribute(hgemm<false, true,  true >,
                         cudaFuncAttributeMaxDynamicSharedMemorySize, GEMM_SMEM_BYTES);

    dim3 blk(256);

    // 1) fused pre-pass
    prep<<<7937, blk>>>(y, yh, Wq, Wk, Wv, wqkvT, Wm, wmT, W1, w1T, W2, w2T,
                        bq, bk, bv, bqkv);

    // 2) Fused QKV: (16384,1536) = gather(yh) @ Wqkv + bqkv -> half
    hgemm<true,  false, true ><<<dim3(12, 128), blk, GEMM_SMEM_BYTES>>>(yh, wqkvT, bqkv, qkv, 16384, 1536, 512);

    // 3) Flash tensor-core attention (pipelined loads) -> att (half)
    attn_mma<<<1024, ATTN_THREADS, ATTN_SMEM_BYTES>>>(qkv, msk, att);

    // 4) Merge: (8192,1024) @ Wm + bm -> half
    hgemm<false, false, true ><<<dim3(8, 64), blk, GEMM_SMEM_BYTES>>>(att, wmT, bm, mh, 8192, 1024, 1024);

    // 5) y1 = LN(y + merge): fp32 (residual) + half (FFN1 input)
    add_ln_kernel<<<8192, blk>>>(y, mh, 1, g1, be1, y1, y1h);

    // 6) FFN1: (8192,1024) @ W1 + b1, relu -> half
    hgemm<false, true,  true ><<<dim3(32, 64), blk, GEMM_SMEM_BYTES>>>(y1h, w1T, b1, h1, 8192, 4096, 1024);

    // 7) FFN2: (16384,2048) @ W2 + b2 -> half
    hgemm<false, false, true ><<<dim3(4, 128), blk, GEMM_SMEM_BYTES>>>(h1, w2T, b2, ff, 16384, 512, 2048);

    // 8) out = LN(y1 + ff), full fp32
    add_ln_kernel<<<8192, blk>>>(y1, ff, 1, g2, be2, out, (__half*)0);
}